// round 4
// baseline (speedup 1.0000x reference)
#include <cuda_runtime.h>
#include <math.h>

#define D_MODEL 2048
#define N_HEADS 16
#define HEAD_DIM 128
#define SEQ 2048
#define BATCH 2
#define M_ROWS (BATCH * SEQ)

// ---------------------------------------------------------------------------
// Scratch (static device arrays; no allocation at kernel_launch time)
// ---------------------------------------------------------------------------
__device__ float g_mha_q[(size_t)BATCH * N_HEADS * SEQ * HEAD_DIM];
__device__ float g_mha_k[(size_t)BATCH * N_HEADS * SEQ * HEAD_DIM];
__device__ float g_mha_v[(size_t)BATCH * N_HEADS * SEQ * HEAD_DIM];
__device__ float g_mha_attn[(size_t)BATCH * SEQ * D_MODEL];

// ---------------------------------------------------------------------------
// SGEMM: C[m,n] = sum_k A[m,k] * B[n,k]   (A: [M,K] row-major, B: [N,K] row-major)
// 128x128 block, K-tile 8, 256 threads, 8x8 per-thread microtile, single-stage
// global->reg prefetch. scatter=1 stores into [B,H,S,hd] layout for Q/K/V.
// ---------------------------------------------------------------------------
__global__ __launch_bounds__(256, 2)
void mha_sgemm_abt(const float* __restrict__ A, const float* __restrict__ B,
                   float* __restrict__ C, int scatter)
{
    const int K = D_MODEL;
    const int N = D_MODEL;
    __shared__ __align__(16) float As[8][128];
    __shared__ __align__(16) float Bs[8][128];

    const int tid = threadIdx.x;
    const int m0 = blockIdx.y * 128;
    const int n0 = blockIdx.x * 128;

    const int lrow = tid >> 1;        // 0..127
    const int lk   = (tid & 1) << 2;  // 0 or 4

    const float* Ap = A + (size_t)(m0 + lrow) * K + lk;
    const float* Bp = B + (size_t)(n0 + lrow) * K + lk;

    float4 aReg = *(const float4*)Ap;
    float4 bReg = *(const float4*)Bp;

    const int ty = tid >> 4;  // 0..15
    const int tx = tid & 15;  // 0..15

    float acc[8][8];
#pragma unroll
    for (int i = 0; i < 8; ++i)
#pragma unroll
        for (int j = 0; j < 8; ++j) acc[i][j] = 0.f;

    const int nk = K >> 3;
    for (int kt = 0; kt < nk; ++kt) {
        As[lk + 0][lrow] = aReg.x;
        As[lk + 1][lrow] = aReg.y;
        As[lk + 2][lrow] = aReg.z;
        As[lk + 3][lrow] = aReg.w;
        Bs[lk + 0][lrow] = bReg.x;
        Bs[lk + 1][lrow] = bReg.y;
        Bs[lk + 2][lrow] = bReg.z;
        Bs[lk + 3][lrow] = bReg.w;
        __syncthreads();
        if (kt + 1 < nk) {
            aReg = *(const float4*)(Ap + (size_t)(kt + 1) * 8);
            bReg = *(const float4*)(Bp + (size_t)(kt + 1) * 8);
        }
#pragma unroll
        for (int kk = 0; kk < 8; ++kk) {
            float a[8], b[8];
            *(float4*)(a)     = *(const float4*)&As[kk][ty * 4];
            *(float4*)(a + 4) = *(const float4*)&As[kk][64 + ty * 4];
            *(float4*)(b)     = *(const float4*)&Bs[kk][tx * 4];
            *(float4*)(b + 4) = *(const float4*)&Bs[kk][64 + tx * 4];
#pragma unroll
            for (int i = 0; i < 8; ++i)
#pragma unroll
                for (int j = 0; j < 8; ++j)
                    acc[i][j] = fmaf(a[i], b[j], acc[i][j]);
        }
        __syncthreads();
    }

#pragma unroll
    for (int i = 0; i < 8; ++i) {
        const int row = m0 + ty * 4 + (i & 3) + ((i >> 2) << 6);
#pragma unroll
        for (int cg = 0; cg < 2; ++cg) {
            const int col = n0 + tx * 4 + (cg << 6);
            float4 v = make_float4(acc[i][cg * 4 + 0], acc[i][cg * 4 + 1],
                                   acc[i][cg * 4 + 2], acc[i][cg * 4 + 3]);
            if (scatter) {
                const int bb = row >> 11;                 // / SEQ
                const int ss = row & (SEQ - 1);
                const int hh = col >> 7;                  // / HEAD_DIM
                const int dd = col & (HEAD_DIM - 1);
                size_t idx = (((size_t)(bb * N_HEADS + hh)) * SEQ + ss) * HEAD_DIM + dd;
                *(float4*)&C[idx] = v;
            } else {
                *(float4*)&C[(size_t)row * N + col] = v;
            }
        }
    }
}

// ---------------------------------------------------------------------------
// RoPE (matches the reference exactly: cos uses freq index (2i)%64, sin uses
// (2i+1)%64 — NOT a standard rotation). In-place on q and k ([B,H,S,hd]).
// ---------------------------------------------------------------------------
__global__ void mha_rope(float* q, float* k)
{
    const int s  = blockIdx.x;
    const int bh = blockIdx.y;
    float* p = (blockIdx.z == 0 ? q : k) + ((size_t)bh * SEQ + s) * HEAD_DIM;
    const int i = threadIdx.x;  // 0..63 (dim pair)
    const int jc = (2 * i) & 63;
    const int js = (2 * i + 1) & 63;
    const float invc = powf(10000.0f, -(float)jc * (1.0f / 64.0f));
    const float invs = powf(10000.0f, -(float)js * (1.0f / 64.0f));
    const float c  = cosf((float)s * invc);
    const float sn = sinf((float)s * invs);
    const float x1 = p[2 * i];
    const float x2 = p[2 * i + 1];
    p[2 * i]     = x1 * c - x2 * sn;
    p[2 * i + 1] = x1 * sn + x2 * c;
}

// ---------------------------------------------------------------------------
// Causal flash attention, fp32 SIMT. BM=BN=64, hd=128, 256 threads.
// Q,K held transposed ([hd][64]) in smem with an XOR swizzle so both the
// transposed fills (scalar STS) and the float4 reads are conflict-light.
// Per-thread 4x4 S-microtile, 4x8 O-microtile; row stats live in registers
// (replicated across the 16 lanes of each row group, via width-16 shuffles).
// Output written to [B,S,H*hd] = row-major [B*S, D] for the final GEMM.
// ---------------------------------------------------------------------------
#define FBM 64
#define FBN 64
#define FT  256

__device__ __forceinline__ int fa_sw(int c, int r)  // c: 0..127, r: 0..63
{
    return (c << 6) + ((((r >> 2) ^ ((c >> 2) & 15)) << 2) | (r & 3));
}

__global__ __launch_bounds__(FT)
void mha_flash(const float* __restrict__ Q, const float* __restrict__ K,
               const float* __restrict__ V, float* __restrict__ Out)
{
    extern __shared__ float sm[];
    float* Qt = sm;                  // 128*64 floats (swizzled, transposed)
    float* Kt = sm + 8192;           // 128*64
    float* Vs = sm + 16384;          // 64*128 (natural layout)
    float* Pt = sm + 24576;          // 64*64  (swizzled, transposed: [col][row])

    const int tid = threadIdx.x;
    const int qb  = blockIdx.x;
    const int bh  = blockIdx.y;
    const int q0  = qb * FBM;

    const float* Qb  = Q + ((size_t)bh * SEQ + q0) * HEAD_DIM;
    const float* Kb0 = K + (size_t)bh * SEQ * HEAD_DIM;
    const float* Vb0 = V + (size_t)bh * SEQ * HEAD_DIM;

    const float scale = 0.08838834764831845f;  // 1/sqrt(128)

    // Load Q tile, transposed + swizzled + pre-scaled
    for (int idx = tid; idx < FBM * HEAD_DIM / 4; idx += FT) {
        const int row = idx >> 5;           // 0..63
        const int c4  = (idx & 31) << 2;    // 0..124
        float4 qv = *(const float4*)(Qb + (size_t)row * HEAD_DIM + c4);
        Qt[fa_sw(c4 + 0, row)] = qv.x * scale;
        Qt[fa_sw(c4 + 1, row)] = qv.y * scale;
        Qt[fa_sw(c4 + 2, row)] = qv.z * scale;
        Qt[fa_sw(c4 + 3, row)] = qv.w * scale;
    }

    const int tr = tid >> 4;  // 0..15  (row group: rows tr*4..tr*4+3)
    const int tc = tid & 15;  // 0..15  (col group)

    float acc[4][8];
#pragma unroll
    for (int i = 0; i < 4; ++i)
#pragma unroll
        for (int j = 0; j < 8; ++j) acc[i][j] = 0.f;
    float m_i[4], l_i[4];
#pragma unroll
    for (int i = 0; i < 4; ++i) { m_i[i] = -INFINITY; l_i[i] = 0.f; }

    for (int kb = 0; kb <= qb; ++kb) {
        const int k0 = kb * FBN;
        __syncthreads();  // protect Kt/Vs/Pt from previous iteration's readers

        const float* Kb = Kb0 + (size_t)k0 * HEAD_DIM;
        const float* Vb = Vb0 + (size_t)k0 * HEAD_DIM;
        for (int idx = tid; idx < FBN * HEAD_DIM / 4; idx += FT) {
            const int row = idx >> 5;
            const int c4  = (idx & 31) << 2;
            float4 kv = *(const float4*)(Kb + (size_t)row * HEAD_DIM + c4);
            Kt[fa_sw(c4 + 0, row)] = kv.x;
            Kt[fa_sw(c4 + 1, row)] = kv.y;
            Kt[fa_sw(c4 + 2, row)] = kv.z;
            Kt[fa_sw(c4 + 3, row)] = kv.w;
            float4 vv = *(const float4*)(Vb + (size_t)row * HEAD_DIM + c4);
            *(float4*)&Vs[row * HEAD_DIM + c4] = vv;
        }
        __syncthreads();

        // ---- S = (Q*scale) @ K^T  (4x4 per thread) ----
        float sfrag[4][4];
#pragma unroll
        for (int i = 0; i < 4; ++i)
#pragma unroll
            for (int j = 0; j < 4; ++j) sfrag[i][j] = 0.f;

#pragma unroll 2
        for (int kg = 0; kg < 32; ++kg) {
            const float* qbase = Qt + (kg << 8) + ((tr ^ (kg & 15)) << 2);
            const float* kbase = Kt + (kg << 8) + ((tc ^ (kg & 15)) << 2);
#pragma unroll
            for (int u = 0; u < 4; ++u) {
                float4 qa = *(const float4*)(qbase + (u << 6));
                float4 kv = *(const float4*)(kbase + (u << 6));
                const float av[4] = {qa.x, qa.y, qa.z, qa.w};
                const float bv[4] = {kv.x, kv.y, kv.z, kv.w};
#pragma unroll
                for (int i = 0; i < 4; ++i)
#pragma unroll
                    for (int j = 0; j < 4; ++j)
                        sfrag[i][j] = fmaf(av[i], bv[j], sfrag[i][j]);
            }
        }

        // ---- causal mask (diagonal block only) ----
        if (kb == qb) {
#pragma unroll
            for (int i = 0; i < 4; ++i)
#pragma unroll
                for (int j = 0; j < 4; ++j)
                    if (k0 + tc * 4 + j > q0 + tr * 4 + i) sfrag[i][j] = -INFINITY;
        }

        // ---- online softmax (stats in registers, shuffles across 16 lanes) ----
#pragma unroll
        for (int i = 0; i < 4; ++i) {
            float mx = fmaxf(fmaxf(sfrag[i][0], sfrag[i][1]),
                             fmaxf(sfrag[i][2], sfrag[i][3]));
#pragma unroll
            for (int off = 8; off > 0; off >>= 1)
                mx = fmaxf(mx, __shfl_xor_sync(0xffffffffu, mx, off, 16));
            const float m_new = fmaxf(m_i[i], mx);
            const float alpha = __expf(m_i[i] - m_new);
            float sum = 0.f;
#pragma unroll
            for (int j = 0; j < 4; ++j) {
                const float p = __expf(sfrag[i][j] - m_new);
                sfrag[i][j] = p;
                sum += p;
            }
#pragma unroll
            for (int off = 8; off > 0; off >>= 1)
                sum += __shfl_xor_sync(0xffffffffu, sum, off, 16);
            l_i[i] = l_i[i] * alpha + sum;
            m_i[i] = m_new;
#pragma unroll
            for (int j = 0; j < 8; ++j) acc[i][j] *= alpha;
            // write P transposed+swizzled: Pt[col][row]
#pragma unroll
            for (int j = 0; j < 4; ++j)
                Pt[(((tc << 2) + j) << 6) + ((tr ^ tc) << 2) + i] = sfrag[i][j];
        }
        __syncthreads();

        // ---- O += P @ V  (4x8 per thread) ----
#pragma unroll 2
        for (int kg = 0; kg < 16; ++kg) {
            const float* pbase = Pt + (kg << 8) + ((tr ^ kg) << 2);
#pragma unroll
            for (int u = 0; u < 4; ++u) {
                const int kk = (kg << 2) + u;
                float4 p4 = *(const float4*)(pbase + (u << 6));
                float4 va = *(const float4*)&Vs[kk * HEAD_DIM + tc * 4];
                float4 vb = *(const float4*)&Vs[kk * HEAD_DIM + 64 + tc * 4];
                const float pv[4]  = {p4.x, p4.y, p4.z, p4.w};
                const float bva[8] = {va.x, va.y, va.z, va.w, vb.x, vb.y, vb.z, vb.w};
#pragma unroll
                for (int i = 0; i < 4; ++i)
#pragma unroll
                    for (int j = 0; j < 8; ++j)
                        acc[i][j] = fmaf(pv[i], bva[j], acc[i][j]);
            }
        }
    }

    // ---- epilogue: normalize and write [B, S, H*hd] ----
    const int b = bh >> 4;
    const int h = bh & 15;
#pragma unroll
    for (int i = 0; i < 4; ++i) {
        const float inv = 1.0f / l_i[i];
        const int row = q0 + tr * 4 + i;
        const size_t base = ((size_t)(b * SEQ + row)) * D_MODEL + h * HEAD_DIM;
#pragma unroll
        for (int cg = 0; cg < 2; ++cg) {
            float4 o = make_float4(acc[i][cg * 4 + 0] * inv, acc[i][cg * 4 + 1] * inv,
                                   acc[i][cg * 4 + 2] * inv, acc[i][cg * 4 + 3] * inv);
            *(float4*)&Out[base + (cg << 6) + tc * 4] = o;
        }
    }
}

// ---------------------------------------------------------------------------
// Launch
// ---------------------------------------------------------------------------
extern "C" void kernel_launch(void* const* d_in, const int* in_sizes, int n_in,
                              void* d_out, int out_size)
{
    (void)in_sizes; (void)n_in; (void)out_size;
    const float* x  = (const float*)d_in[0];
    const float* wq = (const float*)d_in[1];
    const float* wk = (const float*)d_in[2];
    const float* wv = (const float*)d_in[3];
    const float* wo = (const float*)d_in[4];
    // d_in[5] = attn_mask (tril) — causal logic is applied analytically.
    float* out = (float*)d_out;

    float *qp, *kp, *vp, *ap;
    cudaGetSymbolAddress((void**)&qp, g_mha_q);
    cudaGetSymbolAddress((void**)&kp, g_mha_k);
    cudaGetSymbolAddress((void**)&vp, g_mha_v);
    cudaGetSymbolAddress((void**)&ap, g_mha_attn);

    const dim3 gg(D_MODEL / 128, M_ROWS / 128);  // (16, 32)

    mha_sgemm_abt<<<gg, 256>>>(x, wq, qp, 1);
    mha_sgemm_abt<<<gg, 256>>>(x, wk, kp, 1);
    mha_sgemm_abt<<<gg, 256>>>(x, wv, vp, 1);

    mha_rope<<<dim3(SEQ, BATCH * N_HEADS, 2), 64>>>(qp, kp);

    const int flash_smem = (8192 * 3 + 4096) * (int)sizeof(float);  // 114688 B
    cudaFuncSetAttribute(mha_flash, cudaFuncAttributeMaxDynamicSharedMemorySize,
                         flash_smem);
    mha_flash<<<dim3(SEQ / FBM, BATCH * N_HEADS), FT, flash_smem>>>(qp, kp, vp, ap);

    mha_sgemm_abt<<<gg, 256>>>(ap, wo, out, 0);
}

// round 10
// speedup vs baseline: 1.5786x; 1.5786x over previous
#include <cuda_runtime.h>
#include <cuda_bf16.h>
#include <cstdint>
#include <math.h>

#define D_MODEL 2048
#define N_HEADS 16
#define HEAD_DIM 128
#define SEQ 2048
#define BATCH 2
#define M_ROWS (BATCH * SEQ)

// ---------------------------------------------------------------------------
// Scratch (static device arrays; no allocation at kernel_launch time)
// ---------------------------------------------------------------------------
__device__ float g_mha_q[(size_t)BATCH * N_HEADS * SEQ * HEAD_DIM];
__device__ float g_mha_k[(size_t)BATCH * N_HEADS * SEQ * HEAD_DIM];
__device__ float g_mha_v[(size_t)BATCH * N_HEADS * SEQ * HEAD_DIM];
__device__ float g_mha_attn[(size_t)BATCH * SEQ * D_MODEL];

// bf16 hi/lo split buffers
__device__ __nv_bfloat16 g_x_hi[(size_t)M_ROWS * D_MODEL];
__device__ __nv_bfloat16 g_x_lo[(size_t)M_ROWS * D_MODEL];
__device__ __nv_bfloat16 g_wq_hi[(size_t)D_MODEL * D_MODEL];
__device__ __nv_bfloat16 g_wq_lo[(size_t)D_MODEL * D_MODEL];
__device__ __nv_bfloat16 g_wk_hi[(size_t)D_MODEL * D_MODEL];
__device__ __nv_bfloat16 g_wk_lo[(size_t)D_MODEL * D_MODEL];
__device__ __nv_bfloat16 g_wv_hi[(size_t)D_MODEL * D_MODEL];
__device__ __nv_bfloat16 g_wv_lo[(size_t)D_MODEL * D_MODEL];
__device__ __nv_bfloat16 g_wo_hi[(size_t)D_MODEL * D_MODEL];
__device__ __nv_bfloat16 g_wo_lo[(size_t)D_MODEL * D_MODEL];
__device__ __nv_bfloat16 g_a_hi[(size_t)M_ROWS * D_MODEL];
__device__ __nv_bfloat16 g_a_lo[(size_t)M_ROWS * D_MODEL];

// ---------------------------------------------------------------------------
// sm_100-base-target primitives: cp.async, ldmatrix, mma.sync (bf16)
// ---------------------------------------------------------------------------
__device__ __forceinline__ uint32_t smem_u32(const void* p) {
    uint32_t a;
    asm("{ .reg .u64 t; cvta.to.shared.u64 t, %1; cvt.u32.u64 %0, t; }"
        : "=r"(a) : "l"(p));
    return a;
}
__device__ __forceinline__ void cp16(uint32_t s, const void* g) {
    asm volatile("cp.async.cg.shared.global [%0], [%1], 16;"
                 :: "r"(s), "l"(__cvta_generic_to_global(g)) : "memory");
}
#define CPC() asm volatile("cp.async.commit_group;" ::: "memory")
#define CPW(N) asm volatile("cp.async.wait_group %0;" :: "n"(N) : "memory")

#define LDSM4(r0, r1, r2, r3, addr)                                            \
    asm volatile("ldmatrix.sync.aligned.m8n8.x4.shared.b16 {%0,%1,%2,%3}, [%4];" \
                 : "=r"(r0), "=r"(r1), "=r"(r2), "=r"(r3) : "r"(addr))

__device__ __forceinline__ void mma16816(float* d, const uint32_t* a,
                                         const uint32_t* b) {
    asm volatile(
        "mma.sync.aligned.m16n8k16.row.col.f32.bf16.bf16.f32 "
        "{%0,%1,%2,%3}, {%4,%5,%6,%7}, {%8,%9}, {%0,%1,%2,%3};"
        : "+f"(d[0]), "+f"(d[1]), "+f"(d[2]), "+f"(d[3])
        : "r"(a[0]), "r"(a[1]), "r"(a[2]), "r"(a[3]), "r"(b[0]), "r"(b[1]));
}

// Swizzled offset for a 16B chunk within a [128 rows x 64B] tile.
// slot(addr/16 mod 8) = 4*(r&1) + (c ^ ((r>>1)&3)) -> all 8 distinct for any
// 8-row ldmatrix access with fixed c => conflict-free.
__device__ __forceinline__ uint32_t sw_off(int row, int chunk) {
    return (uint32_t)(row * 64 + ((chunk ^ ((row >> 1) & 3)) << 4));
}

// ---------------------------------------------------------------------------
// fp32 -> bf16 hi/lo split (x = hi + lo to ~16 mantissa bits)
// ---------------------------------------------------------------------------
__global__ void mha_split(const float* __restrict__ src,
                          __nv_bfloat16* __restrict__ hi,
                          __nv_bfloat16* __restrict__ lo, int n4)
{
    int i = blockIdx.x * blockDim.x + threadIdx.x;
    if (i >= n4) return;
    float4 v = ((const float4*)src)[i];
    __nv_bfloat16 h0 = __float2bfloat16(v.x), h1 = __float2bfloat16(v.y);
    __nv_bfloat16 h2 = __float2bfloat16(v.z), h3 = __float2bfloat16(v.w);
    __nv_bfloat162* H = (__nv_bfloat162*)hi;
    __nv_bfloat162* L = (__nv_bfloat162*)lo;
    H[i * 2 + 0] = __nv_bfloat162(h0, h1);
    H[i * 2 + 1] = __nv_bfloat162(h2, h3);
    L[i * 2 + 0] = __nv_bfloat162(__float2bfloat16(v.x - __bfloat162float(h0)),
                                  __float2bfloat16(v.y - __bfloat162float(h1)));
    L[i * 2 + 1] = __nv_bfloat162(__float2bfloat16(v.z - __bfloat162float(h2)),
                                  __float2bfloat16(v.w - __bfloat162float(h3)));
}

// ---------------------------------------------------------------------------
// mma.sync bf16 GEMM with hi/lo compensation (3 passes into fp32 accum).
// C[m,n] = sum_k A[m,k]*B[n,k].  Tile 128x128x32, 256 thr (8 warps = 4m x 2n,
// each 32x64). cp.async double-buffered smem. scatter=1 -> [B,H,S,hd] layout.
// ---------------------------------------------------------------------------
#define GSTAGE 32768
#define GSMEM  (2 * GSTAGE)

__global__ __launch_bounds__(256, 1)
void mha_mma_gemm(const __nv_bfloat16* __restrict__ Ahi,
                  const __nv_bfloat16* __restrict__ Alo,
                  const __nv_bfloat16* __restrict__ Bhi,
                  const __nv_bfloat16* __restrict__ Blo,
                  float* __restrict__ C, int scatter)
{
    extern __shared__ char smg[];
    const uint32_t sbase = smem_u32(smg);
    const int K = D_MODEL;
    const int tid  = threadIdx.x;
    const int lane = tid & 31;
    const int wid  = tid >> 5;
    const int warp_m = wid & 3;   // 0..3 -> 32-row slab
    const int warp_n = wid >> 2;  // 0..1 -> 64-col slab
    const int m0 = blockIdx.y * 128;
    const int n0 = blockIdx.x * 128;

    float acc[2][8][4];
#pragma unroll
    for (int mt = 0; mt < 2; ++mt)
#pragma unroll
        for (int nt = 0; nt < 8; ++nt)
#pragma unroll
            for (int e = 0; e < 4; ++e) acc[mt][nt][e] = 0.f;

    // --- async load of one K-chunk (32 cols) into stage s ---
    auto load_chunk = [&](int kc, int s) {
        const uint32_t st = sbase + s * GSTAGE;
#pragma unroll
        for (int i = 0; i < 2; ++i) {
            const int idx = tid + i * 256;
            const int r = idx >> 2;       // 0..127
            const int c = idx & 3;        // 16B chunk
            const uint32_t so = sw_off(r, c);
            const size_t ga = (size_t)(m0 + r) * K + kc + c * 8;
            const size_t gb = (size_t)(n0 + r) * K + kc + c * 8;
            cp16(st + so,         Ahi + ga);
            cp16(st + 8192 + so,  Alo + ga);
            cp16(st + 16384 + so, Bhi + gb);
            cp16(st + 24576 + so, Blo + gb);
        }
    };

    load_chunk(0, 0);
    CPC();

    const int nchunks = K / 32;  // 64
    for (int c = 0; c < nchunks; ++c) {
        const int buf = c & 1;
        if (c + 1 < nchunks) {
            load_chunk((c + 1) * 32, buf ^ 1);
            CPC();
            CPW(1);
        } else {
            CPW(0);
        }
        __syncthreads();

        const uint32_t ab_hi = sbase + buf * GSTAGE;
        const uint32_t ab_lo = ab_hi + 8192;
        const uint32_t bb_hi = ab_hi + 16384;
        const uint32_t bb_lo = ab_hi + 24576;

#pragma unroll
        for (int ks = 0; ks < 2; ++ks) {
            const int ch = ks * 2 + (lane >> 4);
            // A fragments (2 m-tiles, hi+lo)
            uint32_t ah[2][4], al[2][4];
#pragma unroll
            for (int mt = 0; mt < 2; ++mt) {
                const int r = warp_m * 32 + mt * 16 + (lane & 15);
                const uint32_t so = sw_off(r, ch);
                LDSM4(ah[mt][0], ah[mt][1], ah[mt][2], ah[mt][3], ab_hi + so);
                LDSM4(al[mt][0], al[mt][1], al[mt][2], al[mt][3], ab_lo + so);
            }
            // B fragments (8 n-tiles via 4 x4-loads, hi+lo)
            uint32_t bh[8][2], bl[8][2];
#pragma unroll
            for (int nt2 = 0; nt2 < 4; ++nt2) {
                const int r = warp_n * 64 + nt2 * 16 + (lane & 15);
                const uint32_t so = sw_off(r, ch);
                uint32_t t0, t1, t2, t3;
                LDSM4(t0, t1, t2, t3, bb_hi + so);
                bh[nt2 * 2][0] = t0; bh[nt2 * 2][1] = t2;
                bh[nt2 * 2 + 1][0] = t1; bh[nt2 * 2 + 1][1] = t3;
                LDSM4(t0, t1, t2, t3, bb_lo + so);
                bl[nt2 * 2][0] = t0; bl[nt2 * 2][1] = t2;
                bl[nt2 * 2 + 1][0] = t1; bl[nt2 * 2 + 1][1] = t3;
            }
            // pass-major ordering -> 16-mma reuse distance per accumulator
#pragma unroll
            for (int nt = 0; nt < 8; ++nt)
#pragma unroll
                for (int mt = 0; mt < 2; ++mt)
                    mma16816(acc[mt][nt], ah[mt], bh[nt]);
#pragma unroll
            for (int nt = 0; nt < 8; ++nt)
#pragma unroll
                for (int mt = 0; mt < 2; ++mt)
                    mma16816(acc[mt][nt], ah[mt], bl[nt]);
#pragma unroll
            for (int nt = 0; nt < 8; ++nt)
#pragma unroll
                for (int mt = 0; mt < 2; ++mt)
                    mma16816(acc[mt][nt], al[mt], bh[nt]);
        }
        __syncthreads();
    }

    // --- epilogue ---
#pragma unroll
    for (int mt = 0; mt < 2; ++mt) {
#pragma unroll
        for (int half = 0; half < 2; ++half) {
            const int row = m0 + warp_m * 32 + mt * 16 + (lane >> 2) + half * 8;
#pragma unroll
            for (int nt = 0; nt < 8; ++nt) {
                const int col = n0 + warp_n * 64 + nt * 8 + (lane & 3) * 2;
                float2 v = make_float2(acc[mt][nt][half * 2 + 0],
                                       acc[mt][nt][half * 2 + 1]);
                size_t idx;
                if (scatter) {
                    const int bb = row >> 11;
                    const int ss = row & (SEQ - 1);
                    const int hh = col >> 7;
                    const int dd = col & (HEAD_DIM - 1);
                    idx = (((size_t)(bb * N_HEADS + hh)) * SEQ + ss) * HEAD_DIM + dd;
                } else {
                    idx = (size_t)row * D_MODEL + col;
                }
                *(float2*)&C[idx] = v;
            }
        }
    }
}

// ---------------------------------------------------------------------------
// RoPE (matches the reference exactly). In-place on q and k ([B,H,S,hd]).
// ---------------------------------------------------------------------------
__global__ void mha_rope(float* q, float* k)
{
    const int s  = blockIdx.x;
    const int bh = blockIdx.y;
    float* p = (blockIdx.z == 0 ? q : k) + ((size_t)bh * SEQ + s) * HEAD_DIM;
    const int i = threadIdx.x;  // 0..63 (dim pair)
    const int jc = (2 * i) & 63;
    const int js = (2 * i + 1) & 63;
    const float invc = powf(10000.0f, -(float)jc * (1.0f / 64.0f));
    const float invs = powf(10000.0f, -(float)js * (1.0f / 64.0f));
    const float c  = cosf((float)s * invc);
    const float sn = sinf((float)s * invs);
    const float x1 = p[2 * i];
    const float x2 = p[2 * i + 1];
    p[2 * i]     = x1 * c - x2 * sn;
    p[2 * i + 1] = x1 * sn + x2 * c;
}

// ---------------------------------------------------------------------------
// Causal flash attention, fp32 SIMT (unchanged from the passing R4 kernel).
// ---------------------------------------------------------------------------
#define FBM 64
#define FBN 64
#define FT  256

__device__ __forceinline__ int fa_sw(int c, int r)
{
    return (c << 6) + ((((r >> 2) ^ ((c >> 2) & 15)) << 2) | (r & 3));
}

__global__ __launch_bounds__(FT)
void mha_flash(const float* __restrict__ Q, const float* __restrict__ K,
               const float* __restrict__ V, float* __restrict__ Out)
{
    extern __shared__ float smf[];
    float* Qt = smf;
    float* Kt = smf + 8192;
    float* Vs = smf + 16384;
    float* Pt = smf + 24576;

    const int tid = threadIdx.x;
    const int qb  = blockIdx.x;
    const int bh  = blockIdx.y;
    const int q0  = qb * FBM;

    const float* Qb  = Q + ((size_t)bh * SEQ + q0) * HEAD_DIM;
    const float* Kb0 = K + (size_t)bh * SEQ * HEAD_DIM;
    const float* Vb0 = V + (size_t)bh * SEQ * HEAD_DIM;

    const float scale = 0.08838834764831845f;

    for (int idx = tid; idx < FBM * HEAD_DIM / 4; idx += FT) {
        const int row = idx >> 5;
        const int c4  = (idx & 31) << 2;
        float4 qv = *(const float4*)(Qb + (size_t)row * HEAD_DIM + c4);
        Qt[fa_sw(c4 + 0, row)] = qv.x * scale;
        Qt[fa_sw(c4 + 1, row)] = qv.y * scale;
        Qt[fa_sw(c4 + 2, row)] = qv.z * scale;
        Qt[fa_sw(c4 + 3, row)] = qv.w * scale;
    }

    const int tr = tid >> 4;
    const int tc = tid & 15;

    float acc[4][8];
#pragma unroll
    for (int i = 0; i < 4; ++i)
#pragma unroll
        for (int j = 0; j < 8; ++j) acc[i][j] = 0.f;
    float m_i[4], l_i[4];
#pragma unroll
    for (int i = 0; i < 4; ++i) { m_i[i] = -INFINITY; l_i[i] = 0.f; }

    for (int kb = 0; kb <= qb; ++kb) {
        const int k0 = kb * FBN;
        __syncthreads();

        const float* Kb = Kb0 + (size_t)k0 * HEAD_DIM;
        const float* Vb = Vb0 + (size_t)k0 * HEAD_DIM;
        for (int idx = tid; idx < FBN * HEAD_DIM / 4; idx += FT) {
            const int row = idx >> 5;
            const int c4  = (idx & 31) << 2;
            float4 kv = *(const float4*)(Kb + (size_t)row * HEAD_DIM + c4);
            Kt[fa_sw(c4 + 0, row)] = kv.x;
            Kt[fa_sw(c4 + 1, row)] = kv.y;
            Kt[fa_sw(c4 + 2, row)] = kv.z;
            Kt[fa_sw(c4 + 3, row)] = kv.w;
            float4 vv = *(const float4*)(Vb + (size_t)row * HEAD_DIM + c4);
            *(float4*)&Vs[row * HEAD_DIM + c4] = vv;
        }
        __syncthreads();

        float sfrag[4][4];
#pragma unroll
        for (int i = 0; i < 4; ++i)
#pragma unroll
            for (int j = 0; j < 4; ++j) sfrag[i][j] = 0.f;

#pragma unroll 2
        for (int kg = 0; kg < 32; ++kg) {
            const float* qbase = Qt + (kg << 8) + ((tr ^ (kg & 15)) << 2);
            const float* kbase = Kt + (kg << 8) + ((tc ^ (kg & 15)) << 2);
#pragma unroll
            for (int u = 0; u < 4; ++u) {
                float4 qa = *(const float4*)(qbase + (u << 6));
                float4 kv = *(const float4*)(kbase + (u << 6));
                const float av[4] = {qa.x, qa.y, qa.z, qa.w};
                const float bv[4] = {kv.x, kv.y, kv.z, kv.w};
#pragma unroll
                for (int i = 0; i < 4; ++i)
#pragma unroll
                    for (int j = 0; j < 4; ++j)
                        sfrag[i][j] = fmaf(av[i], bv[j], sfrag[i][j]);
            }
        }

        if (kb == qb) {
#pragma unroll
            for (int i = 0; i < 4; ++i)
#pragma unroll
                for (int j = 0; j < 4; ++j)
                    if (k0 + tc * 4 + j > q0 + tr * 4 + i) sfrag[i][j] = -INFINITY;
        }

#pragma unroll
        for (int i = 0; i < 4; ++i) {
            float mx = fmaxf(fmaxf(sfrag[i][0], sfrag[i][1]),
                             fmaxf(sfrag[i][2], sfrag[i][3]));
#pragma unroll
            for (int off = 8; off > 0; off >>= 1)
                mx = fmaxf(mx, __shfl_xor_sync(0xffffffffu, mx, off, 16));
            const float m_new = fmaxf(m_i[i], mx);
            const float alpha = __expf(m_i[i] - m_new);
            float sum = 0.f;
#pragma unroll
            for (int j = 0; j < 4; ++j) {
                const float p = __expf(sfrag[i][j] - m_new);
                sfrag[i][j] = p;
                sum += p;
            }
#pragma unroll
            for (int off = 8; off > 0; off >>= 1)
                sum += __shfl_xor_sync(0xffffffffu, sum, off, 16);
            l_i[i] = l_i[i] * alpha + sum;
            m_i[i] = m_new;
#pragma unroll
            for (int j = 0; j < 8; ++j) acc[i][j] *= alpha;
#pragma unroll
            for (int j = 0; j < 4; ++j)
                Pt[(((tc << 2) + j) << 6) + ((tr ^ tc) << 2) + i] = sfrag[i][j];
        }
        __syncthreads();

#pragma unroll 2
        for (int kg = 0; kg < 16; ++kg) {
            const float* pbase = Pt + (kg << 8) + ((tr ^ kg) << 2);
#pragma unroll
            for (int u = 0; u < 4; ++u) {
                const int kk = (kg << 2) + u;
                float4 p4 = *(const float4*)(pbase + (u << 6));
                float4 va = *(const float4*)&Vs[kk * HEAD_DIM + tc * 4];
                float4 vb = *(const float4*)&Vs[kk * HEAD_DIM + 64 + tc * 4];
                const float pv[4]  = {p4.x, p4.y, p4.z, p4.w};
                const float bva[8] = {va.x, va.y, va.z, va.w, vb.x, vb.y, vb.z, vb.w};
#pragma unroll
                for (int i = 0; i < 4; ++i)
#pragma unroll
                    for (int j = 0; j < 8; ++j)
                        acc[i][j] = fmaf(pv[i], bva[j], acc[i][j]);
            }
        }
    }

    const int b = bh >> 4;
    const int h = bh & 15;
#pragma unroll
    for (int i = 0; i < 4; ++i) {
        const float inv = 1.0f / l_i[i];
        const int row = q0 + tr * 4 + i;
        const size_t base = ((size_t)(b * SEQ + row)) * D_MODEL + h * HEAD_DIM;
#pragma unroll
        for (int cg = 0; cg < 2; ++cg) {
            float4 o = make_float4(acc[i][cg * 4 + 0] * inv, acc[i][cg * 4 + 1] * inv,
                                   acc[i][cg * 4 + 2] * inv, acc[i][cg * 4 + 3] * inv);
            *(float4*)&Out[base + (cg << 6) + tc * 4] = o;
        }
    }
}

// ---------------------------------------------------------------------------
// Launch
// ---------------------------------------------------------------------------
extern "C" void kernel_launch(void* const* d_in, const int* in_sizes, int n_in,
                              void* d_out, int out_size)
{
    (void)in_sizes; (void)n_in; (void)out_size;
    const float* x  = (const float*)d_in[0];
    const float* wq = (const float*)d_in[1];
    const float* wk = (const float*)d_in[2];
    const float* wv = (const float*)d_in[3];
    const float* wo = (const float*)d_in[4];
    float* out = (float*)d_out;

    float *qp, *kp, *vp, *ap;
    cudaGetSymbolAddress((void**)&qp, g_mha_q);
    cudaGetSymbolAddress((void**)&kp, g_mha_k);
    cudaGetSymbolAddress((void**)&vp, g_mha_v);
    cudaGetSymbolAddress((void**)&ap, g_mha_attn);

    __nv_bfloat16 *xh, *xl, *qh, *ql, *kh, *kl, *vh, *vl, *oh, *ol, *ah, *al;
    cudaGetSymbolAddress((void**)&xh, g_x_hi);
    cudaGetSymbolAddress((void**)&xl, g_x_lo);
    cudaGetSymbolAddress((void**)&qh, g_wq_hi);
    cudaGetSymbolAddress((void**)&ql, g_wq_lo);
    cudaGetSymbolAddress((void**)&kh, g_wk_hi);
    cudaGetSymbolAddress((void**)&kl, g_wk_lo);
    cudaGetSymbolAddress((void**)&vh, g_wv_hi);
    cudaGetSymbolAddress((void**)&vl, g_wv_lo);
    cudaGetSymbolAddress((void**)&oh, g_wo_hi);
    cudaGetSymbolAddress((void**)&ol, g_wo_lo);
    cudaGetSymbolAddress((void**)&ah, g_a_hi);
    cudaGetSymbolAddress((void**)&al, g_a_lo);

    const int nx4 = M_ROWS * D_MODEL / 4;   // 2,097,152
    const int nw4 = D_MODEL * D_MODEL / 4;  // 1,048,576

    mha_split<<<nx4 / 256, 256>>>(x, xh, xl, nx4);
    mha_split<<<nw4 / 256, 256>>>(wq, qh, ql, nw4);
    mha_split<<<nw4 / 256, 256>>>(wk, kh, kl, nw4);
    mha_split<<<nw4 / 256, 256>>>(wv, vh, vl, nw4);
    mha_split<<<nw4 / 256, 256>>>(wo, oh, ol, nw4);

    cudaFuncSetAttribute(mha_mma_gemm, cudaFuncAttributeMaxDynamicSharedMemorySize,
                         GSMEM);
    const dim3 gg(D_MODEL / 128, M_ROWS / 128);  // (16, 32)

    mha_mma_gemm<<<gg, 256, GSMEM>>>(xh, xl, qh, ql, qp, 1);
    mha_mma_gemm<<<gg, 256, GSMEM>>>(xh, xl, kh, kl, kp, 1);
    mha_mma_gemm<<<gg, 256, GSMEM>>>(xh, xl, vh, vl, vp, 1);

    mha_rope<<<dim3(SEQ, BATCH * N_HEADS, 2), 64>>>(qp, kp);

    const int flash_smem = (8192 * 3 + 4096) * (int)sizeof(float);  // 114688 B
    cudaFuncSetAttribute(mha_flash, cudaFuncAttributeMaxDynamicSharedMemorySize,
                         flash_smem);
    mha_flash<<<dim3(SEQ / FBM, BATCH * N_HEADS), FT, flash_smem>>>(qp, kp, vp, ap);

    mha_split<<<nx4 / 256, 256>>>(ap, ah, al, nx4);
    mha_mma_gemm<<<gg, 256, GSMEM>>>(ah, al, oh, ol, out, 0);
}

// round 11
// speedup vs baseline: 1.9225x; 1.2179x over previous
#include <cuda_runtime.h>
#include <cuda_fp16.h>
#include <cstdint>
#include <math.h>

#define D_MODEL 2048
#define N_HEADS 16
#define HEAD_DIM 128
#define SEQ 2048
#define BATCH 2
#define M_ROWS (BATCH * SEQ)

// ---------------------------------------------------------------------------
// Scratch (static device arrays; no allocation at kernel_launch time)
// ---------------------------------------------------------------------------
__device__ float g_mha_q[(size_t)BATCH * N_HEADS * SEQ * HEAD_DIM];
__device__ float g_mha_k[(size_t)BATCH * N_HEADS * SEQ * HEAD_DIM];
__device__ float g_mha_v[(size_t)BATCH * N_HEADS * SEQ * HEAD_DIM];
__device__ float g_mha_attn[(size_t)BATCH * SEQ * D_MODEL];

// fp16 buffers: activations hi/lo (2-pass compensation), weights single fp16
__device__ __half g_x_hi[(size_t)M_ROWS * D_MODEL];
__device__ __half g_x_lo[(size_t)M_ROWS * D_MODEL];
__device__ __half g_a_hi[(size_t)M_ROWS * D_MODEL];
__device__ __half g_a_lo[(size_t)M_ROWS * D_MODEL];
__device__ __half g_wq_h[(size_t)D_MODEL * D_MODEL];
__device__ __half g_wk_h[(size_t)D_MODEL * D_MODEL];
__device__ __half g_wv_h[(size_t)D_MODEL * D_MODEL];
__device__ __half g_wo_h[(size_t)D_MODEL * D_MODEL];

// ---------------------------------------------------------------------------
// sm_100-base-target primitives: cp.async, ldmatrix, mma.sync (fp16)
// ---------------------------------------------------------------------------
__device__ __forceinline__ uint32_t smem_u32(const void* p) {
    uint32_t a;
    asm("{ .reg .u64 t; cvta.to.shared.u64 t, %1; cvt.u32.u64 %0, t; }"
        : "=r"(a) : "l"(p));
    return a;
}
__device__ __forceinline__ void cp16(uint32_t s, const void* g) {
    asm volatile("cp.async.cg.shared.global [%0], [%1], 16;"
                 :: "r"(s), "l"(__cvta_generic_to_global(g)) : "memory");
}
#define CPC() asm volatile("cp.async.commit_group;" ::: "memory")
#define CPW(N) asm volatile("cp.async.wait_group %0;" :: "n"(N) : "memory")

#define LDSM4(r0, r1, r2, r3, addr)                                            \
    asm volatile("ldmatrix.sync.aligned.m8n8.x4.shared.b16 {%0,%1,%2,%3}, [%4];" \
                 : "=r"(r0), "=r"(r1), "=r"(r2), "=r"(r3) : "r"(addr))

__device__ __forceinline__ void mma16816(float* d, const uint32_t* a,
                                         const uint32_t* b) {
    asm volatile(
        "mma.sync.aligned.m16n8k16.row.col.f32.f16.f16.f32 "
        "{%0,%1,%2,%3}, {%4,%5,%6,%7}, {%8,%9}, {%0,%1,%2,%3};"
        : "+f"(d[0]), "+f"(d[1]), "+f"(d[2]), "+f"(d[3])
        : "r"(a[0]), "r"(a[1]), "r"(a[2]), "r"(a[3]), "r"(b[0]), "r"(b[1]));
}

// Swizzled offset for a 16B chunk within a [128 rows x 64B] tile.
// slot(addr/16 mod 8) = 4*(r&1) + (c ^ ((r>>1)&3)) -> all 8 distinct for any
// 8-row ldmatrix access with fixed c => conflict-free.
__device__ __forceinline__ uint32_t sw_off(int row, int chunk) {
    return (uint32_t)(row * 64 + ((chunk ^ ((row >> 1) & 3)) << 4));
}

// ---------------------------------------------------------------------------
// fp32 -> fp16 hi/lo split (x = hi + lo to ~22 mantissa bits)
// ---------------------------------------------------------------------------
__global__ void mha_split16(const float* __restrict__ src,
                            __half* __restrict__ hi,
                            __half* __restrict__ lo, int n4)
{
    int i = blockIdx.x * blockDim.x + threadIdx.x;
    if (i >= n4) return;
    float4 v = ((const float4*)src)[i];
    __half h0 = __float2half(v.x), h1 = __float2half(v.y);
    __half h2 = __float2half(v.z), h3 = __float2half(v.w);
    __half2* H = (__half2*)hi;
    __half2* L = (__half2*)lo;
    H[i * 2 + 0] = __halves2half2(h0, h1);
    H[i * 2 + 1] = __halves2half2(h2, h3);
    L[i * 2 + 0] = __halves2half2(__float2half(v.x - __half2float(h0)),
                                  __float2half(v.y - __half2float(h1)));
    L[i * 2 + 1] = __halves2half2(__float2half(v.z - __half2float(h2)),
                                  __float2half(v.w - __half2float(h3)));
}

// fp32 -> fp16 plain convert (weights: single-operand error ~2^-11 random)
__global__ void mha_cvt16(const float* __restrict__ src,
                          __half* __restrict__ dst, int n4)
{
    int i = blockIdx.x * blockDim.x + threadIdx.x;
    if (i >= n4) return;
    float4 v = ((const float4*)src)[i];
    __half2* D = (__half2*)dst;
    D[i * 2 + 0] = __floats2half2_rn(v.x, v.y);
    D[i * 2 + 1] = __floats2half2_rn(v.z, v.w);
}

// ---------------------------------------------------------------------------
// mma.sync fp16 GEMM, 2-pass compensation: C = (A_hi + A_lo) @ B^T.
// C[m,n] = sum_k A[m,k]*B[n,k].  Tile 128x128x32, 256 thr (8 warps = 4m x 2n,
// each 32x64). cp.async double-buffered smem. scatter=1 -> [B,H,S,hd] layout.
// ---------------------------------------------------------------------------
#define GSTAGE 24576         // A_hi 8K + A_lo 8K + B 8K
#define GSMEM  (2 * GSTAGE)  // 48 KB -> 2 CTAs/SM by smem

__global__ __launch_bounds__(256, 2)
void mha_mma_gemm(const __half* __restrict__ Ahi,
                  const __half* __restrict__ Alo,
                  const __half* __restrict__ Bh,
                  float* __restrict__ C, int scatter)
{
    extern __shared__ char smg[];
    const uint32_t sbase = smem_u32(smg);
    const int K = D_MODEL;
    const int tid  = threadIdx.x;
    const int lane = tid & 31;
    const int wid  = tid >> 5;
    const int warp_m = wid & 3;   // 0..3 -> 32-row slab
    const int warp_n = wid >> 2;  // 0..1 -> 64-col slab
    const int m0 = blockIdx.y * 128;
    const int n0 = blockIdx.x * 128;

    float acc[2][8][4];
#pragma unroll
    for (int mt = 0; mt < 2; ++mt)
#pragma unroll
        for (int nt = 0; nt < 8; ++nt)
#pragma unroll
            for (int e = 0; e < 4; ++e) acc[mt][nt][e] = 0.f;

    // --- async load of one K-chunk (32 cols) into stage s ---
    auto load_chunk = [&](int kc, int s) {
        const uint32_t st = sbase + s * GSTAGE;
#pragma unroll
        for (int i = 0; i < 2; ++i) {
            const int idx = tid + i * 256;
            const int r = idx >> 2;       // 0..127
            const int c = idx & 3;        // 16B chunk
            const uint32_t so = sw_off(r, c);
            const size_t ga = (size_t)(m0 + r) * K + kc + c * 8;
            const size_t gb = (size_t)(n0 + r) * K + kc + c * 8;
            cp16(st + so,         Ahi + ga);
            cp16(st + 8192 + so,  Alo + ga);
            cp16(st + 16384 + so, Bh + gb);
        }
    };

    load_chunk(0, 0);
    CPC();

    const int nchunks = K / 32;  // 64
    for (int c = 0; c < nchunks; ++c) {
        const int buf = c & 1;
        if (c + 1 < nchunks) {
            load_chunk((c + 1) * 32, buf ^ 1);
            CPC();
            CPW(1);
        } else {
            CPW(0);
        }
        __syncthreads();

        const uint32_t ab_hi = sbase + buf * GSTAGE;
        const uint32_t ab_lo = ab_hi + 8192;
        const uint32_t bb_hi = ab_hi + 16384;

#pragma unroll
        for (int ks = 0; ks < 2; ++ks) {
            const int ch = ks * 2 + (lane >> 4);
            // A fragments (2 m-tiles, hi+lo)
            uint32_t ah[2][4], al[2][4];
#pragma unroll
            for (int mt = 0; mt < 2; ++mt) {
                const int r = warp_m * 32 + mt * 16 + (lane & 15);
                const uint32_t so = sw_off(r, ch);
                LDSM4(ah[mt][0], ah[mt][1], ah[mt][2], ah[mt][3], ab_hi + so);
                LDSM4(al[mt][0], al[mt][1], al[mt][2], al[mt][3], ab_lo + so);
            }
            // B fragments (8 n-tiles via 4 x4-loads, hi only)
            uint32_t bh[8][2];
#pragma unroll
            for (int nt2 = 0; nt2 < 4; ++nt2) {
                const int r = warp_n * 64 + nt2 * 16 + (lane & 15);
                const uint32_t so = sw_off(r, ch);
                uint32_t t0, t1, t2, t3;
                LDSM4(t0, t1, t2, t3, bb_hi + so);
                bh[nt2 * 2][0] = t0; bh[nt2 * 2][1] = t2;
                bh[nt2 * 2 + 1][0] = t1; bh[nt2 * 2 + 1][1] = t3;
            }
            // 2 passes: A_hi*B, A_lo*B  (16-mma reuse distance per accum)
#pragma unroll
            for (int nt = 0; nt < 8; ++nt)
#pragma unroll
                for (int mt = 0; mt < 2; ++mt)
                    mma16816(acc[mt][nt], ah[mt], bh[nt]);
#pragma unroll
            for (int nt = 0; nt < 8; ++nt)
#pragma unroll
                for (int mt = 0; mt < 2; ++mt)
                    mma16816(acc[mt][nt], al[mt], bh[nt]);
        }
        __syncthreads();
    }

    // --- epilogue ---
#pragma unroll
    for (int mt = 0; mt < 2; ++mt) {
#pragma unroll
        for (int half = 0; half < 2; ++half) {
            const int row = m0 + warp_m * 32 + mt * 16 + (lane >> 2) + half * 8;
#pragma unroll
            for (int nt = 0; nt < 8; ++nt) {
                const int col = n0 + warp_n * 64 + nt * 8 + (lane & 3) * 2;
                float2 v = make_float2(acc[mt][nt][half * 2 + 0],
                                       acc[mt][nt][half * 2 + 1]);
                size_t idx;
                if (scatter) {
                    const int bb = row >> 11;
                    const int ss = row & (SEQ - 1);
                    const int hh = col >> 7;
                    const int dd = col & (HEAD_DIM - 1);
                    idx = (((size_t)(bb * N_HEADS + hh)) * SEQ + ss) * HEAD_DIM + dd;
                } else {
                    idx = (size_t)row * D_MODEL + col;
                }
                *(float2*)&C[idx] = v;
            }
        }
    }
}

// ---------------------------------------------------------------------------
// RoPE (matches the reference exactly). In-place on q and k ([B,H,S,hd]).
// ---------------------------------------------------------------------------
__global__ void mha_rope(float* q, float* k)
{
    const int s  = blockIdx.x;
    const int bh = blockIdx.y;
    float* p = (blockIdx.z == 0 ? q : k) + ((size_t)bh * SEQ + s) * HEAD_DIM;
    const int i = threadIdx.x;  // 0..63 (dim pair)
    const int jc = (2 * i) & 63;
    const int js = (2 * i + 1) & 63;
    const float invc = powf(10000.0f, -(float)jc * (1.0f / 64.0f));
    const float invs = powf(10000.0f, -(float)js * (1.0f / 64.0f));
    const float c  = cosf((float)s * invc);
    const float sn = sinf((float)s * invs);
    const float x1 = p[2 * i];
    const float x2 = p[2 * i + 1];
    p[2 * i]     = x1 * c - x2 * sn;
    p[2 * i + 1] = x1 * sn + x2 * c;
}

// ---------------------------------------------------------------------------
// Causal flash attention, fp32 SIMT (unchanged from the passing R10 kernel).
// ---------------------------------------------------------------------------
#define FBM 64
#define FBN 64
#define FT  256

__device__ __forceinline__ int fa_sw(int c, int r)
{
    return (c << 6) + ((((r >> 2) ^ ((c >> 2) & 15)) << 2) | (r & 3));
}

__global__ __launch_bounds__(FT)
void mha_flash(const float* __restrict__ Q, const float* __restrict__ K,
               const float* __restrict__ V, float* __restrict__ Out)
{
    extern __shared__ float smf[];
    float* Qt = smf;
    float* Kt = smf + 8192;
    float* Vs = smf + 16384;
    float* Pt = smf + 24576;

    const int tid = threadIdx.x;
    const int qb  = blockIdx.x;
    const int bh  = blockIdx.y;
    const int q0  = qb * FBM;

    const float* Qb  = Q + ((size_t)bh * SEQ + q0) * HEAD_DIM;
    const float* Kb0 = K + (size_t)bh * SEQ * HEAD_DIM;
    const float* Vb0 = V + (size_t)bh * SEQ * HEAD_DIM;

    const float scale = 0.08838834764831845f;

    for (int idx = tid; idx < FBM * HEAD_DIM / 4; idx += FT) {
        const int row = idx >> 5;
        const int c4  = (idx & 31) << 2;
        float4 qv = *(const float4*)(Qb + (size_t)row * HEAD_DIM + c4);
        Qt[fa_sw(c4 + 0, row)] = qv.x * scale;
        Qt[fa_sw(c4 + 1, row)] = qv.y * scale;
        Qt[fa_sw(c4 + 2, row)] = qv.z * scale;
        Qt[fa_sw(c4 + 3, row)] = qv.w * scale;
    }

    const int tr = tid >> 4;
    const int tc = tid & 15;

    float acc[4][8];
#pragma unroll
    for (int i = 0; i < 4; ++i)
#pragma unroll
        for (int j = 0; j < 8; ++j) acc[i][j] = 0.f;
    float m_i[4], l_i[4];
#pragma unroll
    for (int i = 0; i < 4; ++i) { m_i[i] = -INFINITY; l_i[i] = 0.f; }

    for (int kb = 0; kb <= qb; ++kb) {
        const int k0 = kb * FBN;
        __syncthreads();

        const float* Kb = Kb0 + (size_t)k0 * HEAD_DIM;
        const float* Vb = Vb0 + (size_t)k0 * HEAD_DIM;
        for (int idx = tid; idx < FBN * HEAD_DIM / 4; idx += FT) {
            const int row = idx >> 5;
            const int c4  = (idx & 31) << 2;
            float4 kv = *(const float4*)(Kb + (size_t)row * HEAD_DIM + c4);
            Kt[fa_sw(c4 + 0, row)] = kv.x;
            Kt[fa_sw(c4 + 1, row)] = kv.y;
            Kt[fa_sw(c4 + 2, row)] = kv.z;
            Kt[fa_sw(c4 + 3, row)] = kv.w;
            float4 vv = *(const float4*)(Vb + (size_t)row * HEAD_DIM + c4);
            *(float4*)&Vs[row * HEAD_DIM + c4] = vv;
        }
        __syncthreads();

        float sfrag[4][4];
#pragma unroll
        for (int i = 0; i < 4; ++i)
#pragma unroll
            for (int j = 0; j < 4; ++j) sfrag[i][j] = 0.f;

#pragma unroll 2
        for (int kg = 0; kg < 32; ++kg) {
            const float* qbase = Qt + (kg << 8) + ((tr ^ (kg & 15)) << 2);
            const float* kbase = Kt + (kg << 8) + ((tc ^ (kg & 15)) << 2);
#pragma unroll
            for (int u = 0; u < 4; ++u) {
                float4 qa = *(const float4*)(qbase + (u << 6));
                float4 kv = *(const float4*)(kbase + (u << 6));
                const float av[4] = {qa.x, qa.y, qa.z, qa.w};
                const float bv[4] = {kv.x, kv.y, kv.z, kv.w};
#pragma unroll
                for (int i = 0; i < 4; ++i)
#pragma unroll
                    for (int j = 0; j < 4; ++j)
                        sfrag[i][j] = fmaf(av[i], bv[j], sfrag[i][j]);
            }
        }

        if (kb == qb) {
#pragma unroll
            for (int i = 0; i < 4; ++i)
#pragma unroll
                for (int j = 0; j < 4; ++j)
                    if (k0 + tc * 4 + j > q0 + tr * 4 + i) sfrag[i][j] = -INFINITY;
        }

#pragma unroll
        for (int i = 0; i < 4; ++i) {
            float mx = fmaxf(fmaxf(sfrag[i][0], sfrag[i][1]),
                             fmaxf(sfrag[i][2], sfrag[i][3]));
#pragma unroll
            for (int off = 8; off > 0; off >>= 1)
                mx = fmaxf(mx, __shfl_xor_sync(0xffffffffu, mx, off, 16));
            const float m_new = fmaxf(m_i[i], mx);
            const float alpha = __expf(m_i[i] - m_new);
            float sum = 0.f;
#pragma unroll
            for (int j = 0; j < 4; ++j) {
                const float p = __expf(sfrag[i][j] - m_new);
                sfrag[i][j] = p;
                sum += p;
            }
#pragma unroll
            for (int off = 8; off > 0; off >>= 1)
                sum += __shfl_xor_sync(0xffffffffu, sum, off, 16);
            l_i[i] = l_i[i] * alpha + sum;
            m_i[i] = m_new;
#pragma unroll
            for (int j = 0; j < 8; ++j) acc[i][j] *= alpha;
#pragma unroll
            for (int j = 0; j < 4; ++j)
                Pt[(((tc << 2) + j) << 6) + ((tr ^ tc) << 2) + i] = sfrag[i][j];
        }
        __syncthreads();

#pragma unroll 2
        for (int kg = 0; kg < 16; ++kg) {
            const float* pbase = Pt + (kg << 8) + ((tr ^ kg) << 2);
#pragma unroll
            for (int u = 0; u < 4; ++u) {
                const int kk = (kg << 2) + u;
                float4 p4 = *(const float4*)(pbase + (u << 6));
                float4 va = *(const float4*)&Vs[kk * HEAD_DIM + tc * 4];
                float4 vb = *(const float4*)&Vs[kk * HEAD_DIM + 64 + tc * 4];
                const float pv[4]  = {p4.x, p4.y, p4.z, p4.w};
                const float bva[8] = {va.x, va.y, va.z, va.w, vb.x, vb.y, vb.z, vb.w};
#pragma unroll
                for (int i = 0; i < 4; ++i)
#pragma unroll
                    for (int j = 0; j < 8; ++j)
                        acc[i][j] = fmaf(pv[i], bva[j], acc[i][j]);
            }
        }
    }

    const int b = bh >> 4;
    const int h = bh & 15;
#pragma unroll
    for (int i = 0; i < 4; ++i) {
        const float inv = 1.0f / l_i[i];
        const int row = q0 + tr * 4 + i;
        const size_t base = ((size_t)(b * SEQ + row)) * D_MODEL + h * HEAD_DIM;
#pragma unroll
        for (int cg = 0; cg < 2; ++cg) {
            float4 o = make_float4(acc[i][cg * 4 + 0] * inv, acc[i][cg * 4 + 1] * inv,
                                   acc[i][cg * 4 + 2] * inv, acc[i][cg * 4 + 3] * inv);
            *(float4*)&Out[base + (cg << 6) + tc * 4] = o;
        }
    }
}

// ---------------------------------------------------------------------------
// Launch
// ---------------------------------------------------------------------------
extern "C" void kernel_launch(void* const* d_in, const int* in_sizes, int n_in,
                              void* d_out, int out_size)
{
    (void)in_sizes; (void)n_in; (void)out_size;
    const float* x  = (const float*)d_in[0];
    const float* wq = (const float*)d_in[1];
    const float* wk = (const float*)d_in[2];
    const float* wv = (const float*)d_in[3];
    const float* wo = (const float*)d_in[4];
    float* out = (float*)d_out;

    float *qp, *kp, *vp, *ap;
    cudaGetSymbolAddress((void**)&qp, g_mha_q);
    cudaGetSymbolAddress((void**)&kp, g_mha_k);
    cudaGetSymbolAddress((void**)&vp, g_mha_v);
    cudaGetSymbolAddress((void**)&ap, g_mha_attn);

    __half *xh, *xl, *ah, *al, *wqh, *wkh, *wvh, *woh;
    cudaGetSymbolAddress((void**)&xh, g_x_hi);
    cudaGetSymbolAddress((void**)&xl, g_x_lo);
    cudaGetSymbolAddress((void**)&ah, g_a_hi);
    cudaGetSymbolAddress((void**)&al, g_a_lo);
    cudaGetSymbolAddress((void**)&wqh, g_wq_h);
    cudaGetSymbolAddress((void**)&wkh, g_wk_h);
    cudaGetSymbolAddress((void**)&wvh, g_wv_h);
    cudaGetSymbolAddress((void**)&woh, g_wo_h);

    const int nx4 = M_ROWS * D_MODEL / 4;   // 2,097,152
    const int nw4 = D_MODEL * D_MODEL / 4;  // 1,048,576

    mha_split16<<<nx4 / 256, 256>>>(x, xh, xl, nx4);
    mha_cvt16<<<nw4 / 256, 256>>>(wq, wqh, nw4);
    mha_cvt16<<<nw4 / 256, 256>>>(wk, wkh, nw4);
    mha_cvt16<<<nw4 / 256, 256>>>(wv, wvh, nw4);
    mha_cvt16<<<nw4 / 256, 256>>>(wo, woh, nw4);

    cudaFuncSetAttribute(mha_mma_gemm, cudaFuncAttributeMaxDynamicSharedMemorySize,
                         GSMEM);
    const dim3 gg(D_MODEL / 128, M_ROWS / 128);  // (16, 32)

    mha_mma_gemm<<<gg, 256, GSMEM>>>(xh, xl, wqh, qp, 1);
    mha_mma_gemm<<<gg, 256, GSMEM>>>(xh, xl, wkh, kp, 1);
    mha_mma_gemm<<<gg, 256, GSMEM>>>(xh, xl, wvh, vp, 1);

    mha_rope<<<dim3(SEQ, BATCH * N_HEADS, 2), 64>>>(qp, kp);

    const int flash_smem = (8192 * 3 + 4096) * (int)sizeof(float);  // 114688 B
    cudaFuncSetAttribute(mha_flash, cudaFuncAttributeMaxDynamicSharedMemorySize,
                         flash_smem);
    mha_flash<<<dim3(SEQ / FBM, BATCH * N_HEADS), FT, flash_smem>>>(qp, kp, vp, ap);

    mha_split16<<<nx4 / 256, 256>>>(ap, ah, al, nx4);
    mha_mma_gemm<<<gg, 256, GSMEM>>>(ah, al, woh, out, 0);
}

// round 12
// speedup vs baseline: 3.1857x; 1.6571x over previous
#include <cuda_runtime.h>
#include <cuda_fp16.h>
#include <cstdint>
#include <math.h>

#define D_MODEL 2048
#define N_HEADS 16
#define HEAD_DIM 128
#define SEQ 2048
#define BATCH 2
#define M_ROWS (BATCH * SEQ)
#define BH (BATCH * N_HEADS)

// ---------------------------------------------------------------------------
// Scratch (static device arrays; no allocation at kernel_launch time)
// ---------------------------------------------------------------------------
__device__ float g_mha_q[(size_t)BH * SEQ * HEAD_DIM];
__device__ float g_mha_k[(size_t)BH * SEQ * HEAD_DIM];
__device__ float g_mha_v[(size_t)BH * SEQ * HEAD_DIM];
__device__ float g_mha_attn[(size_t)BATCH * SEQ * D_MODEL];

// fp16 buffers
__device__ __half g_x_hi[(size_t)M_ROWS * D_MODEL];
__device__ __half g_x_lo[(size_t)M_ROWS * D_MODEL];
__device__ __half g_a_hi[(size_t)M_ROWS * D_MODEL];
__device__ __half g_a_lo[(size_t)M_ROWS * D_MODEL];
__device__ __half g_wq_h[(size_t)D_MODEL * D_MODEL];
__device__ __half g_wk_h[(size_t)D_MODEL * D_MODEL];
__device__ __half g_wv_h[(size_t)D_MODEL * D_MODEL];
__device__ __half g_wo_h[(size_t)D_MODEL * D_MODEL];
// attention operands, fp16 hi/lo (Q pre-scaled, post-RoPE); V transposed
__device__ __half g_q16h[(size_t)BH * SEQ * HEAD_DIM];
__device__ __half g_q16l[(size_t)BH * SEQ * HEAD_DIM];
__device__ __half g_k16h[(size_t)BH * SEQ * HEAD_DIM];
__device__ __half g_k16l[(size_t)BH * SEQ * HEAD_DIM];
__device__ __half g_vt16h[(size_t)BH * HEAD_DIM * SEQ];
__device__ __half g_vt16l[(size_t)BH * HEAD_DIM * SEQ];

// ---------------------------------------------------------------------------
// primitives: cp.async, ldmatrix, mma.sync (fp16)
// ---------------------------------------------------------------------------
__device__ __forceinline__ uint32_t smem_u32(const void* p) {
    uint32_t a;
    asm("{ .reg .u64 t; cvta.to.shared.u64 t, %1; cvt.u32.u64 %0, t; }"
        : "=r"(a) : "l"(p));
    return a;
}
__device__ __forceinline__ void cp16(uint32_t s, const void* g) {
    asm volatile("cp.async.cg.shared.global [%0], [%1], 16;"
                 :: "r"(s), "l"(__cvta_generic_to_global(g)) : "memory");
}
#define CPC() asm volatile("cp.async.commit_group;" ::: "memory")
#define CPW(N) asm volatile("cp.async.wait_group %0;" :: "n"(N) : "memory")

#define LDSM4(r0, r1, r2, r3, addr)                                            \
    asm volatile("ldmatrix.sync.aligned.m8n8.x4.shared.b16 {%0,%1,%2,%3}, [%4];" \
                 : "=r"(r0), "=r"(r1), "=r"(r2), "=r"(r3) : "r"(addr))

__device__ __forceinline__ void mma16816(float* d, const uint32_t* a,
                                         const uint32_t* b) {
    asm volatile(
        "mma.sync.aligned.m16n8k16.row.col.f32.f16.f16.f32 "
        "{%0,%1,%2,%3}, {%4,%5,%6,%7}, {%8,%9}, {%0,%1,%2,%3};"
        : "+f"(d[0]), "+f"(d[1]), "+f"(d[2]), "+f"(d[3])
        : "r"(a[0]), "r"(a[1]), "r"(a[2]), "r"(a[3]), "r"(b[0]), "r"(b[1]));
}

// swizzles: 64B-row tiles (GEMM), 256B-row tiles (Q/K), 128B-row tiles (Vt)
__device__ __forceinline__ uint32_t sw_off(int row, int chunk) {
    return (uint32_t)(row * 64 + ((chunk ^ ((row >> 1) & 3)) << 4));
}
__device__ __forceinline__ uint32_t qsw(int r, int c) {   // r<64, c<16
    return (uint32_t)((r << 8) + ((c ^ (r & 7)) << 4));
}
__device__ __forceinline__ uint32_t vsw(int r, int c) {   // r<128, c<8
    return (uint32_t)((r << 7) + ((c ^ (r & 7)) << 4));
}

// ---------------------------------------------------------------------------
// fp32 -> fp16 hi/lo split, and plain convert
// ---------------------------------------------------------------------------
__global__ void mha_split16(const float* __restrict__ src,
                            __half* __restrict__ hi,
                            __half* __restrict__ lo, int n4)
{
    int i = blockIdx.x * blockDim.x + threadIdx.x;
    if (i >= n4) return;
    float4 v = ((const float4*)src)[i];
    __half h0 = __float2half(v.x), h1 = __float2half(v.y);
    __half h2 = __float2half(v.z), h3 = __float2half(v.w);
    __half2* H = (__half2*)hi;
    __half2* L = (__half2*)lo;
    H[i * 2 + 0] = __halves2half2(h0, h1);
    H[i * 2 + 1] = __halves2half2(h2, h3);
    L[i * 2 + 0] = __halves2half2(__float2half(v.x - __half2float(h0)),
                                  __float2half(v.y - __half2float(h1)));
    L[i * 2 + 1] = __halves2half2(__float2half(v.z - __half2float(h2)),
                                  __float2half(v.w - __half2float(h3)));
}

__global__ void mha_cvt16(const float* __restrict__ src,
                          __half* __restrict__ dst, int n4)
{
    int i = blockIdx.x * blockDim.x + threadIdx.x;
    if (i >= n4) return;
    float4 v = ((const float4*)src)[i];
    __half2* D = (__half2*)dst;
    D[i * 2 + 0] = __floats2half2_rn(v.x, v.y);
    D[i * 2 + 1] = __floats2half2_rn(v.z, v.w);
}

// ---------------------------------------------------------------------------
// mma.sync fp16 GEMM, 2-pass compensation (unchanged from R11).
// ---------------------------------------------------------------------------
#define GSTAGE 24576
#define GSMEM  (2 * GSTAGE)

__global__ __launch_bounds__(256, 2)
void mha_mma_gemm(const __half* __restrict__ Ahi,
                  const __half* __restrict__ Alo,
                  const __half* __restrict__ Bh,
                  float* __restrict__ C, int scatter)
{
    extern __shared__ char smg[];
    const uint32_t sbase = smem_u32(smg);
    const int K = D_MODEL;
    const int tid  = threadIdx.x;
    const int lane = tid & 31;
    const int wid  = tid >> 5;
    const int warp_m = wid & 3;
    const int warp_n = wid >> 2;
    const int m0 = blockIdx.y * 128;
    const int n0 = blockIdx.x * 128;

    float acc[2][8][4];
#pragma unroll
    for (int mt = 0; mt < 2; ++mt)
#pragma unroll
        for (int nt = 0; nt < 8; ++nt)
#pragma unroll
            for (int e = 0; e < 4; ++e) acc[mt][nt][e] = 0.f;

    auto load_chunk = [&](int kc, int s) {
        const uint32_t st = sbase + s * GSTAGE;
#pragma unroll
        for (int i = 0; i < 2; ++i) {
            const int idx = tid + i * 256;
            const int r = idx >> 2;
            const int c = idx & 3;
            const uint32_t so = sw_off(r, c);
            const size_t ga = (size_t)(m0 + r) * K + kc + c * 8;
            const size_t gb = (size_t)(n0 + r) * K + kc + c * 8;
            cp16(st + so,         Ahi + ga);
            cp16(st + 8192 + so,  Alo + ga);
            cp16(st + 16384 + so, Bh + gb);
        }
    };

    load_chunk(0, 0);
    CPC();

    const int nchunks = K / 32;
    for (int c = 0; c < nchunks; ++c) {
        const int buf = c & 1;
        if (c + 1 < nchunks) {
            load_chunk((c + 1) * 32, buf ^ 1);
            CPC();
            CPW(1);
        } else {
            CPW(0);
        }
        __syncthreads();

        const uint32_t ab_hi = sbase + buf * GSTAGE;
        const uint32_t ab_lo = ab_hi + 8192;
        const uint32_t bb_hi = ab_hi + 16384;

#pragma unroll
        for (int ks = 0; ks < 2; ++ks) {
            const int ch = ks * 2 + (lane >> 4);
            uint32_t ah[2][4], al[2][4];
#pragma unroll
            for (int mt = 0; mt < 2; ++mt) {
                const int r = warp_m * 32 + mt * 16 + (lane & 15);
                const uint32_t so = sw_off(r, ch);
                LDSM4(ah[mt][0], ah[mt][1], ah[mt][2], ah[mt][3], ab_hi + so);
                LDSM4(al[mt][0], al[mt][1], al[mt][2], al[mt][3], ab_lo + so);
            }
            uint32_t bh[8][2];
#pragma unroll
            for (int nt2 = 0; nt2 < 4; ++nt2) {
                const int r = warp_n * 64 + nt2 * 16 + (lane & 15);
                const uint32_t so = sw_off(r, ch);
                uint32_t t0, t1, t2, t3;
                LDSM4(t0, t1, t2, t3, bb_hi + so);
                bh[nt2 * 2][0] = t0; bh[nt2 * 2][1] = t2;
                bh[nt2 * 2 + 1][0] = t1; bh[nt2 * 2 + 1][1] = t3;
            }
#pragma unroll
            for (int nt = 0; nt < 8; ++nt)
#pragma unroll
                for (int mt = 0; mt < 2; ++mt)
                    mma16816(acc[mt][nt], ah[mt], bh[nt]);
#pragma unroll
            for (int nt = 0; nt < 8; ++nt)
#pragma unroll
                for (int mt = 0; mt < 2; ++mt)
                    mma16816(acc[mt][nt], al[mt], bh[nt]);
        }
        __syncthreads();
    }

#pragma unroll
    for (int mt = 0; mt < 2; ++mt) {
#pragma unroll
        for (int half = 0; half < 2; ++half) {
            const int row = m0 + warp_m * 32 + mt * 16 + (lane >> 2) + half * 8;
#pragma unroll
            for (int nt = 0; nt < 8; ++nt) {
                const int col = n0 + warp_n * 64 + nt * 8 + (lane & 3) * 2;
                float2 v = make_float2(acc[mt][nt][half * 2 + 0],
                                       acc[mt][nt][half * 2 + 1]);
                size_t idx;
                if (scatter) {
                    const int bb = row >> 11;
                    const int ss = row & (SEQ - 1);
                    const int hh = col >> 7;
                    const int dd = col & (HEAD_DIM - 1);
                    idx = (((size_t)(bb * N_HEADS + hh)) * SEQ + ss) * HEAD_DIM + dd;
                } else {
                    idx = (size_t)row * D_MODEL + col;
                }
                *(float2*)&C[idx] = v;
            }
        }
    }
}

// ---------------------------------------------------------------------------
// RoPE + fp16 hi/lo convert. z=0: Q (scaled by 1/sqrt(hd)); z=1: K.
// ---------------------------------------------------------------------------
__global__ void mha_ropecvt16(const float* __restrict__ q,
                              const float* __restrict__ k,
                              __half* __restrict__ qh, __half* __restrict__ ql,
                              __half* __restrict__ kh, __half* __restrict__ kl)
{
    const int s  = blockIdx.x;
    const int bh = blockIdx.y;
    const int z  = blockIdx.z;
    const size_t off = ((size_t)bh * SEQ + s) * HEAD_DIM;
    const float* src = (z ? k : q) + off;
    __half* oh = (z ? kh : qh) + off;
    __half* ol = (z ? kl : ql) + off;
    const int i = threadIdx.x;  // 0..63
    const int jc = (2 * i) & 63;
    const int js = (2 * i + 1) & 63;
    const float invc = powf(10000.0f, -(float)jc * (1.0f / 64.0f));
    const float invs = powf(10000.0f, -(float)js * (1.0f / 64.0f));
    const float c  = cosf((float)s * invc);
    const float sn = sinf((float)s * invs);
    const float x1 = src[2 * i];
    const float x2 = src[2 * i + 1];
    const float scl = z ? 1.0f : 0.08838834764831845f;
    const float r1 = (x1 * c - x2 * sn) * scl;
    const float r2 = (x1 * sn + x2 * c) * scl;
    const __half h1 = __float2half(r1);
    const __half h2 = __float2half(r2);
    ((__half2*)oh)[i] = __halves2half2(h1, h2);
    ((__half2*)ol)[i] = __halves2half2(__float2half(r1 - __half2float(h1)),
                                       __float2half(r2 - __half2float(h2)));
}

// ---------------------------------------------------------------------------
// V fp32 [bh][s][d] -> transposed fp16 hi/lo [bh][d][s] (32x32 smem tiles)
// ---------------------------------------------------------------------------
__global__ void mha_cvtT16(const float* __restrict__ V,
                           __half* __restrict__ vth, __half* __restrict__ vtl)
{
    __shared__ float t[32][33];
    const int bh = blockIdx.z;
    const int s0 = blockIdx.x * 32;
    const int d0 = blockIdx.y * 32;
    const int tx = threadIdx.x, ty = threadIdx.y;  // (32, 8)
    const float* Vb = V + (size_t)bh * SEQ * HEAD_DIM;
#pragma unroll
    for (int i = 0; i < 4; ++i)
        t[ty + 8 * i][tx] = Vb[(size_t)(s0 + ty + 8 * i) * HEAD_DIM + d0 + tx];
    __syncthreads();
    __half* oh = vth + (size_t)bh * HEAD_DIM * SEQ;
    __half* ol = vtl + (size_t)bh * HEAD_DIM * SEQ;
#pragma unroll
    for (int i = 0; i < 4; ++i) {
        const int d = d0 + ty + 8 * i;
        const float v = t[tx][ty + 8 * i];
        const __half h = __float2half(v);
        oh[(size_t)d * SEQ + s0 + tx] = h;
        ol[(size_t)d * SEQ + s0 + tx] = __float2half(v - __half2float(h));
    }
}

// ---------------------------------------------------------------------------
// Tensor-core causal flash attention. BM=BN=64, 128 thr (4 warps x 16 rows).
// S = (Qhi+Qlo)(Khi+Klo)^T via 3 passes; O += (Phi+Plo)(Vhi+Vlo) via 3 passes.
// S-accumulator fragments reused directly as P A-fragments (FA2 identity).
// Single K/V stage (96 KB smem), 2 CTAs/SM for cross-CTA overlap.
// ---------------------------------------------------------------------------
#define FA_SQH 0
#define FA_SQL 16384
#define FA_SKH 32768
#define FA_SKL 49152
#define FA_SVH 65536
#define FA_SVL 81920
#define FA_SMEM 98304

__global__ __launch_bounds__(128, 2)
void mha_flash_mma(const __half* __restrict__ qh, const __half* __restrict__ ql,
                   const __half* __restrict__ kh, const __half* __restrict__ kl,
                   const __half* __restrict__ vth, const __half* __restrict__ vtl,
                   float* __restrict__ Out)
{
    extern __shared__ char smfa[];
    const uint32_t sb = smem_u32(smfa);
    const int tid  = threadIdx.x;
    const int lane = tid & 31;
    const int w    = tid >> 5;
    const int qb   = blockIdx.x;
    const int bh   = blockIdx.y;
    const int q0   = qb * 64;

    const size_t qoff = ((size_t)bh * SEQ + q0) * HEAD_DIM;
    const __half* Qh = qh + qoff;
    const __half* Ql = ql + qoff;
    const __half* Kb_h = kh + (size_t)bh * SEQ * HEAD_DIM;
    const __half* Kb_l = kl + (size_t)bh * SEQ * HEAD_DIM;
    const __half* Vb_h = vth + (size_t)bh * HEAD_DIM * SEQ;
    const __half* Vb_l = vtl + (size_t)bh * HEAD_DIM * SEQ;

    // load Q tile (64x128 fp16 hi/lo) once
#pragma unroll
    for (int i = 0; i < 8; ++i) {
        const int idx = tid + i * 128;
        const int r = idx >> 4;
        const int c = idx & 15;
        cp16(sb + FA_SQH + qsw(r, c), Qh + (size_t)r * HEAD_DIM + c * 8);
        cp16(sb + FA_SQL + qsw(r, c), Ql + (size_t)r * HEAD_DIM + c * 8);
    }

    float oacc[16][4];
#pragma unroll
    for (int nt = 0; nt < 16; ++nt)
#pragma unroll
        for (int e = 0; e < 4; ++e) oacc[nt][e] = 0.f;
    float m0v = -INFINITY, m1v = -INFINITY, l0v = 0.f, l1v = 0.f;

    for (int kb = 0; kb <= qb; ++kb) {
        const int k0 = kb * 64;
        __syncthreads();  // prior compute done before overwriting K/V stage
        // load K (64x128 hi/lo) and Vt (128x64 hi/lo)
#pragma unroll
        for (int i = 0; i < 8; ++i) {
            const int idx = tid + i * 128;
            const int r = idx >> 4;
            const int c = idx & 15;
            cp16(sb + FA_SKH + qsw(r, c), Kb_h + (size_t)(k0 + r) * HEAD_DIM + c * 8);
            cp16(sb + FA_SKL + qsw(r, c), Kb_l + (size_t)(k0 + r) * HEAD_DIM + c * 8);
            const int rv = idx >> 3;
            const int cv = idx & 7;
            cp16(sb + FA_SVH + vsw(rv, cv), Vb_h + (size_t)rv * SEQ + k0 + cv * 8);
            cp16(sb + FA_SVL + vsw(rv, cv), Vb_l + (size_t)rv * SEQ + k0 + cv * 8);
        }
        CPC();
        CPW(0);
        __syncthreads();

        // ---- S = Q K^T, 3-pass ----
        float sacc[8][4];
#pragma unroll
        for (int nt = 0; nt < 8; ++nt)
#pragma unroll
            for (int e = 0; e < 4; ++e) sacc[nt][e] = 0.f;

#pragma unroll
        for (int ks = 0; ks < 8; ++ks) {
            const int ch = ks * 2 + (lane >> 4);
            uint32_t aqh[4], aql[4];
            {
                const uint32_t so = qsw(16 * w + (lane & 15), ch);
                LDSM4(aqh[0], aqh[1], aqh[2], aqh[3], sb + FA_SQH + so);
                LDSM4(aql[0], aql[1], aql[2], aql[3], sb + FA_SQL + so);
            }
            uint32_t bkh[8][2], bkl[8][2];
#pragma unroll
            for (int nt2 = 0; nt2 < 4; ++nt2) {
                const uint32_t so = qsw(nt2 * 16 + (lane & 15), ch);
                uint32_t t0, t1, t2, t3;
                LDSM4(t0, t1, t2, t3, sb + FA_SKH + so);
                bkh[nt2 * 2][0] = t0; bkh[nt2 * 2][1] = t2;
                bkh[nt2 * 2 + 1][0] = t1; bkh[nt2 * 2 + 1][1] = t3;
                LDSM4(t0, t1, t2, t3, sb + FA_SKL + so);
                bkl[nt2 * 2][0] = t0; bkl[nt2 * 2][1] = t2;
                bkl[nt2 * 2 + 1][0] = t1; bkl[nt2 * 2 + 1][1] = t3;
            }
#pragma unroll
            for (int nt = 0; nt < 8; ++nt) {
                mma16816(sacc[nt], aqh, bkh[nt]);
                mma16816(sacc[nt], aqh, bkl[nt]);
                mma16816(sacc[nt], aql, bkh[nt]);
            }
        }

        // ---- causal mask (diagonal block) ----
        const int row0 = q0 + 16 * w + (lane >> 2);
        if (kb == qb) {
#pragma unroll
            for (int nt = 0; nt < 8; ++nt)
#pragma unroll
                for (int e = 0; e < 4; ++e) {
                    const int col = k0 + nt * 8 + (lane & 3) * 2 + (e & 1);
                    const int row = row0 + (e >> 1) * 8;
                    if (col > row) sacc[nt][e] = -INFINITY;
                }
        }

        // ---- online softmax (rows row0 and row0+8) ----
        float rmax0 = -INFINITY, rmax1 = -INFINITY;
#pragma unroll
        for (int nt = 0; nt < 8; ++nt) {
            rmax0 = fmaxf(rmax0, fmaxf(sacc[nt][0], sacc[nt][1]));
            rmax1 = fmaxf(rmax1, fmaxf(sacc[nt][2], sacc[nt][3]));
        }
        rmax0 = fmaxf(rmax0, __shfl_xor_sync(0xffffffffu, rmax0, 1));
        rmax0 = fmaxf(rmax0, __shfl_xor_sync(0xffffffffu, rmax0, 2));
        rmax1 = fmaxf(rmax1, __shfl_xor_sync(0xffffffffu, rmax1, 1));
        rmax1 = fmaxf(rmax1, __shfl_xor_sync(0xffffffffu, rmax1, 2));
        const float mn0 = fmaxf(m0v, rmax0);
        const float mn1 = fmaxf(m1v, rmax1);
        const float al0 = __expf(m0v - mn0);
        const float al1 = __expf(m1v - mn1);
        m0v = mn0; m1v = mn1;
        float rs0 = 0.f, rs1 = 0.f;
#pragma unroll
        for (int nt = 0; nt < 8; ++nt) {
            sacc[nt][0] = __expf(sacc[nt][0] - mn0);
            sacc[nt][1] = __expf(sacc[nt][1] - mn0);
            sacc[nt][2] = __expf(sacc[nt][2] - mn1);
            sacc[nt][3] = __expf(sacc[nt][3] - mn1);
            rs0 += sacc[nt][0] + sacc[nt][1];
            rs1 += sacc[nt][2] + sacc[nt][3];
        }
        rs0 += __shfl_xor_sync(0xffffffffu, rs0, 1);
        rs0 += __shfl_xor_sync(0xffffffffu, rs0, 2);
        rs1 += __shfl_xor_sync(0xffffffffu, rs1, 1);
        rs1 += __shfl_xor_sync(0xffffffffu, rs1, 2);
        l0v = l0v * al0 + rs0;
        l1v = l1v * al1 + rs1;
#pragma unroll
        for (int nt = 0; nt < 16; ++nt) {
            oacc[nt][0] *= al0; oacc[nt][1] *= al0;
            oacc[nt][2] *= al1; oacc[nt][3] *= al1;
        }

        // ---- P fragments (hi/lo), S-accum -> A-frag identity ----
        uint32_t pfh[4][4], pfl[4][4];
#pragma unroll
        for (int kc = 0; kc < 4; ++kc) {
#pragma unroll
            for (int e = 0; e < 4; ++e) {
                const int t  = 2 * kc + (e >> 1);
                const int e0 = (e & 1) * 2;
                const float p0 = sacc[t][e0], p1 = sacc[t][e0 + 1];
                const __half h0 = __float2half(p0), h1 = __float2half(p1);
                __half2 hv = __halves2half2(h0, h1);
                __half2 lv = __halves2half2(__float2half(p0 - __half2float(h0)),
                                            __float2half(p1 - __half2float(h1)));
                // A-frag order: a0=(r,k),a1=(r+8,k),a2=(r,k+8),a3=(r+8,k+8)
                const int slot = ((e >> 1) << 1) | (e & 1);  // t-major -> a-index
                pfh[kc][slot] = *(uint32_t*)&hv;
                pfl[kc][slot] = *(uint32_t*)&lv;
            }
        }

        // ---- O += P V, 3-pass ----
#pragma unroll
        for (int kc = 0; kc < 4; ++kc) {
#pragma unroll
            for (int g = 0; g < 8; ++g) {
                const uint32_t so = vsw(g * 16 + (lane & 15), kc * 2 + (lane >> 4));
                uint32_t t0, t1, t2, t3;
                uint32_t b0h[2], b1h[2], b0l[2], b1l[2];
                LDSM4(t0, t1, t2, t3, sb + FA_SVH + so);
                b0h[0] = t0; b0h[1] = t2; b1h[0] = t1; b1h[1] = t3;
                LDSM4(t0, t1, t2, t3, sb + FA_SVL + so);
                b0l[0] = t0; b0l[1] = t2; b1l[0] = t1; b1l[1] = t3;
                mma16816(oacc[2 * g],     pfh[kc], b0h);
                mma16816(oacc[2 * g],     pfh[kc], b0l);
                mma16816(oacc[2 * g],     pfl[kc], b0h);
                mma16816(oacc[2 * g + 1], pfh[kc], b1h);
                mma16816(oacc[2 * g + 1], pfh[kc], b1l);
                mma16816(oacc[2 * g + 1], pfl[kc], b1h);
            }
        }
    }

    // ---- epilogue: O /= l, write [b][s][h*128 + d] ----
    const float inv0 = 1.0f / l0v;
    const float inv1 = 1.0f / l1v;
    const int b = bh >> 4;
    const int h = bh & 15;
    const int row0 = q0 + 16 * w + (lane >> 2);
#pragma unroll
    for (int nt = 0; nt < 16; ++nt) {
        const int col = h * HEAD_DIM + nt * 8 + (lane & 3) * 2;
        const size_t i0 = ((size_t)(b * SEQ + row0)) * D_MODEL + col;
        const size_t i1 = ((size_t)(b * SEQ + row0 + 8)) * D_MODEL + col;
        *(float2*)&Out[i0] = make_float2(oacc[nt][0] * inv0, oacc[nt][1] * inv0);
        *(float2*)&Out[i1] = make_float2(oacc[nt][2] * inv1, oacc[nt][3] * inv1);
    }
}

// ---------------------------------------------------------------------------
// Launch
// ---------------------------------------------------------------------------
extern "C" void kernel_launch(void* const* d_in, const int* in_sizes, int n_in,
                              void* d_out, int out_size)
{
    (void)in_sizes; (void)n_in; (void)out_size;
    const float* x  = (const float*)d_in[0];
    const float* wq = (const float*)d_in[1];
    const float* wk = (const float*)d_in[2];
    const float* wv = (const float*)d_in[3];
    const float* wo = (const float*)d_in[4];
    float* out = (float*)d_out;

    float *qp, *kp, *vp, *ap;
    cudaGetSymbolAddress((void**)&qp, g_mha_q);
    cudaGetSymbolAddress((void**)&kp, g_mha_k);
    cudaGetSymbolAddress((void**)&vp, g_mha_v);
    cudaGetSymbolAddress((void**)&ap, g_mha_attn);

    __half *xh, *xl, *ah, *al, *wqh, *wkh, *wvh, *woh;
    cudaGetSymbolAddress((void**)&xh, g_x_hi);
    cudaGetSymbolAddress((void**)&xl, g_x_lo);
    cudaGetSymbolAddress((void**)&ah, g_a_hi);
    cudaGetSymbolAddress((void**)&al, g_a_lo);
    cudaGetSymbolAddress((void**)&wqh, g_wq_h);
    cudaGetSymbolAddress((void**)&wkh, g_wk_h);
    cudaGetSymbolAddress((void**)&wvh, g_wv_h);
    cudaGetSymbolAddress((void**)&woh, g_wo_h);

    __half *q16h, *q16l, *k16h, *k16l, *vt16h, *vt16l;
    cudaGetSymbolAddress((void**)&q16h, g_q16h);
    cudaGetSymbolAddress((void**)&q16l, g_q16l);
    cudaGetSymbolAddress((void**)&k16h, g_k16h);
    cudaGetSymbolAddress((void**)&k16l, g_k16l);
    cudaGetSymbolAddress((void**)&vt16h, g_vt16h);
    cudaGetSymbolAddress((void**)&vt16l, g_vt16l);

    const int nx4 = M_ROWS * D_MODEL / 4;
    const int nw4 = D_MODEL * D_MODEL / 4;

    mha_split16<<<nx4 / 256, 256>>>(x, xh, xl, nx4);
    mha_cvt16<<<nw4 / 256, 256>>>(wq, wqh, nw4);
    mha_cvt16<<<nw4 / 256, 256>>>(wk, wkh, nw4);
    mha_cvt16<<<nw4 / 256, 256>>>(wv, wvh, nw4);
    mha_cvt16<<<nw4 / 256, 256>>>(wo, woh, nw4);

    cudaFuncSetAttribute(mha_mma_gemm, cudaFuncAttributeMaxDynamicSharedMemorySize,
                         GSMEM);
    const dim3 gg(D_MODEL / 128, M_ROWS / 128);

    mha_mma_gemm<<<gg, 256, GSMEM>>>(xh, xl, wqh, qp, 1);
    mha_mma_gemm<<<gg, 256, GSMEM>>>(xh, xl, wkh, kp, 1);
    mha_mma_gemm<<<gg, 256, GSMEM>>>(xh, xl, wvh, vp, 1);

    mha_ropecvt16<<<dim3(SEQ, BH, 2), 64>>>(qp, kp, q16h, q16l, k16h, k16l);
    mha_cvtT16<<<dim3(SEQ / 32, HEAD_DIM / 32, BH), dim3(32, 8)>>>(vp, vt16h, vt16l);

    cudaFuncSetAttribute(mha_flash_mma, cudaFuncAttributeMaxDynamicSharedMemorySize,
                         FA_SMEM);
    mha_flash_mma<<<dim3(SEQ / 64, BH), 128, FA_SMEM>>>(q16h, q16l, k16h, k16l,
                                                        vt16h, vt16l, ap);

    mha_split16<<<nx4 / 256, 256>>>(ap, ah, al, nx4);
    mha_mma_gemm<<<gg, 256, GSMEM>>>(ah, al, woh, out, 0);
}

// round 13
// speedup vs baseline: 3.6814x; 1.1556x over previous
#include <cuda_runtime.h>
#include <cuda_fp16.h>
#include <cstdint>
#include <math.h>

#define D_MODEL 2048
#define N_HEADS 16
#define HEAD_DIM 128
#define SEQ 2048
#define BATCH 2
#define M_ROWS (BATCH * SEQ)
#define BH (BATCH * N_HEADS)

// ---------------------------------------------------------------------------
// Scratch (static device arrays; no allocation at kernel_launch time)
// ---------------------------------------------------------------------------
__device__ __half g_x_hi[(size_t)M_ROWS * D_MODEL];
__device__ __half g_x_lo[(size_t)M_ROWS * D_MODEL];
__device__ __half g_a_hi[(size_t)M_ROWS * D_MODEL];
__device__ __half g_a_lo[(size_t)M_ROWS * D_MODEL];
__device__ __half g_wq_h[(size_t)D_MODEL * D_MODEL];
__device__ __half g_wk_h[(size_t)D_MODEL * D_MODEL];
__device__ __half g_wv_h[(size_t)D_MODEL * D_MODEL];
__device__ __half g_wo_h[(size_t)D_MODEL * D_MODEL];
__device__ __half g_q16h[(size_t)BH * SEQ * HEAD_DIM];
__device__ __half g_q16l[(size_t)BH * SEQ * HEAD_DIM];
__device__ __half g_k16h[(size_t)BH * SEQ * HEAD_DIM];
__device__ __half g_k16l[(size_t)BH * SEQ * HEAD_DIM];
__device__ __half g_v16h[(size_t)BH * SEQ * HEAD_DIM];
__device__ __half g_v16l[(size_t)BH * SEQ * HEAD_DIM];
__device__ __half g_vt16h[(size_t)BH * HEAD_DIM * SEQ];
__device__ __half g_vt16l[(size_t)BH * HEAD_DIM * SEQ];
__device__ float g_ropec[SEQ * 64];
__device__ float g_ropes[SEQ * 64];

// ---------------------------------------------------------------------------
// primitives
// ---------------------------------------------------------------------------
__device__ __forceinline__ uint32_t smem_u32(const void* p) {
    uint32_t a;
    asm("{ .reg .u64 t; cvta.to.shared.u64 t, %1; cvt.u32.u64 %0, t; }"
        : "=r"(a) : "l"(p));
    return a;
}
__device__ __forceinline__ void cp16(uint32_t s, const void* g) {
    asm volatile("cp.async.cg.shared.global [%0], [%1], 16;"
                 :: "r"(s), "l"(__cvta_generic_to_global(g)) : "memory");
}
#define CPC() asm volatile("cp.async.commit_group;" ::: "memory")
#define CPW(N) asm volatile("cp.async.wait_group %0;" :: "n"(N) : "memory")

#define LDSM4(r0, r1, r2, r3, addr)                                            \
    asm volatile("ldmatrix.sync.aligned.m8n8.x4.shared.b16 {%0,%1,%2,%3}, [%4];" \
                 : "=r"(r0), "=r"(r1), "=r"(r2), "=r"(r3) : "r"(addr))

__device__ __forceinline__ void mma16816(float* d, const uint32_t* a,
                                         const uint32_t* b) {
    asm volatile(
        "mma.sync.aligned.m16n8k16.row.col.f32.f16.f16.f32 "
        "{%0,%1,%2,%3}, {%4,%5,%6,%7}, {%8,%9}, {%0,%1,%2,%3};"
        : "+f"(d[0]), "+f"(d[1]), "+f"(d[2]), "+f"(d[3])
        : "r"(a[0]), "r"(a[1]), "r"(a[2]), "r"(a[3]), "r"(b[0]), "r"(b[1]));
}

// swizzles: 128B-row (GEMM K-chunk 64), 256B-row (Q/K flash), 128B-row (Vt)
__device__ __forceinline__ uint32_t g128(int r, int c) {  // r<128, c<8
    return (uint32_t)((r << 7) + ((c ^ (r & 7)) << 4));
}
__device__ __forceinline__ uint32_t qsw(int r, int c) {   // r<64, c<16
    return (uint32_t)((r << 8) + ((c ^ (r & 7)) << 4));
}
__device__ __forceinline__ uint32_t vsw(int r, int c) {   // r<128, c<8
    return (uint32_t)((r << 7) + ((c ^ (r & 7)) << 4));
}

__device__ __forceinline__ void split_h2(float a, float b, __half2& h, __half2& l)
{
    const __half h0 = __float2half(a), h1 = __float2half(b);
    h = __halves2half2(h0, h1);
    l = __halves2half2(__float2half(a - __half2float(h0)),
                       __float2half(b - __half2float(h1)));
}

// ---------------------------------------------------------------------------
// converts + RoPE tables
// ---------------------------------------------------------------------------
__global__ void mha_split16(const float* __restrict__ src,
                            __half* __restrict__ hi,
                            __half* __restrict__ lo, int n4)
{
    int i = blockIdx.x * blockDim.x + threadIdx.x;
    if (i >= n4) return;
    float4 v = ((const float4*)src)[i];
    __half2 h0, l0, h1, l1;
    split_h2(v.x, v.y, h0, l0);
    split_h2(v.z, v.w, h1, l1);
    ((__half2*)hi)[i * 2 + 0] = h0;
    ((__half2*)hi)[i * 2 + 1] = h1;
    ((__half2*)lo)[i * 2 + 0] = l0;
    ((__half2*)lo)[i * 2 + 1] = l1;
}

__global__ void mha_cvt16(const float* __restrict__ src,
                          __half* __restrict__ dst, int n4)
{
    int i = blockIdx.x * blockDim.x + threadIdx.x;
    if (i >= n4) return;
    float4 v = ((const float4*)src)[i];
    __half2* D = (__half2*)dst;
    D[i * 2 + 0] = __floats2half2_rn(v.x, v.y);
    D[i * 2 + 1] = __floats2half2_rn(v.z, v.w);
}

__global__ void mha_rope_tables(float* __restrict__ rc, float* __restrict__ rs)
{
    const int s = blockIdx.x;
    const int i = threadIdx.x;  // 0..63
    const int jc = (2 * i) & 63;
    const int js = (2 * i + 1) & 63;
    const float invc = powf(10000.0f, -(float)jc * (1.0f / 64.0f));
    const float invs = powf(10000.0f, -(float)js * (1.0f / 64.0f));
    rc[s * 64 + i] = cosf((float)s * invc);
    rs[s * 64 + i] = sinf((float)s * invs);
}

// ---------------------------------------------------------------------------
// Templated GEMM: C[m,n] = sum_k A[m,k]*B[n,k]. Tile 128x128, K-chunk 64,
// 256 thr (8 warps 4m x 2n), double-buffered cp.async.
// NPASS: 2 = (A_hi+A_lo)@B, 1 = A_hi@B.
// MODE: 0 = fp32 row-major out; 1 = RoPE+scale, fp16 hi/lo scatter to
//       [bh][s][hd]; 2 = fp16 hi/lo scatter to [bh][s][hd].
// ---------------------------------------------------------------------------
#define GSTAGE 49152
#define GSMEM  (2 * GSTAGE)

template <int MODE, int NPASS>
__global__ __launch_bounds__(256, 2)
void gemm_t(const __half* __restrict__ Ahi, const __half* __restrict__ Alo,
            const __half* __restrict__ Bh, float* __restrict__ C,
            __half* __restrict__ OH, __half* __restrict__ OL, float scale,
            const float* __restrict__ rc, const float* __restrict__ rs)
{
    extern __shared__ char smg[];
    const uint32_t sbase = smem_u32(smg);
    const int K = D_MODEL;
    const int tid  = threadIdx.x;
    const int lane = tid & 31;
    const int wid  = tid >> 5;
    const int warp_m = wid & 3;
    const int warp_n = wid >> 2;
    const int m0 = blockIdx.y * 128;
    const int n0 = blockIdx.x * 128;

    float acc[2][8][4];
#pragma unroll
    for (int mt = 0; mt < 2; ++mt)
#pragma unroll
        for (int nt = 0; nt < 8; ++nt)
#pragma unroll
            for (int e = 0; e < 4; ++e) acc[mt][nt][e] = 0.f;

    auto load_chunk = [&](int kc, int s) {
        const uint32_t st = sbase + s * GSTAGE;
#pragma unroll
        for (int i = 0; i < 4; ++i) {
            const int idx = tid + i * 256;   // 0..1023
            const int r = idx >> 3;          // 0..127
            const int c = idx & 7;           // 16B chunk
            const uint32_t so = g128(r, c);
            const size_t ga = (size_t)(m0 + r) * K + kc + c * 8;
            const size_t gb = (size_t)(n0 + r) * K + kc + c * 8;
            cp16(st + so, Ahi + ga);
            if (NPASS == 2) cp16(st + 16384 + so, Alo + ga);
            cp16(st + 32768 + so, Bh + gb);
        }
    };

    load_chunk(0, 0);
    CPC();

    const int nchunks = K / 64;  // 32
    for (int c = 0; c < nchunks; ++c) {
        const int buf = c & 1;
        if (c + 1 < nchunks) {
            load_chunk((c + 1) * 64, buf ^ 1);
            CPC();
            CPW(1);
        } else {
            CPW(0);
        }
        __syncthreads();

        const uint32_t ab_hi = sbase + buf * GSTAGE;
        const uint32_t ab_lo = ab_hi + 16384;
        const uint32_t bb_hi = ab_hi + 32768;

#pragma unroll
        for (int ks = 0; ks < 4; ++ks) {
            const int ch = ks * 2 + (lane >> 4);
            uint32_t ah[2][4], al[2][4];
#pragma unroll
            for (int mt = 0; mt < 2; ++mt) {
                const int r = warp_m * 32 + mt * 16 + (lane & 15);
                const uint32_t so = g128(r, ch);
                LDSM4(ah[mt][0], ah[mt][1], ah[mt][2], ah[mt][3], ab_hi + so);
                if (NPASS == 2)
                    LDSM4(al[mt][0], al[mt][1], al[mt][2], al[mt][3], ab_lo + so);
            }
            uint32_t bh[8][2];
#pragma unroll
            for (int nt2 = 0; nt2 < 4; ++nt2) {
                const int r = warp_n * 64 + nt2 * 16 + (lane & 15);
                const uint32_t so = g128(r, ch);
                uint32_t t0, t1, t2, t3;
                LDSM4(t0, t1, t2, t3, bb_hi + so);
                bh[nt2 * 2][0] = t0; bh[nt2 * 2][1] = t2;
                bh[nt2 * 2 + 1][0] = t1; bh[nt2 * 2 + 1][1] = t3;
            }
#pragma unroll
            for (int nt = 0; nt < 8; ++nt)
#pragma unroll
                for (int mt = 0; mt < 2; ++mt)
                    mma16816(acc[mt][nt], ah[mt], bh[nt]);
            if (NPASS == 2) {
#pragma unroll
                for (int nt = 0; nt < 8; ++nt)
#pragma unroll
                    for (int mt = 0; mt < 2; ++mt)
                        mma16816(acc[mt][nt], al[mt], bh[nt]);
            }
        }
        __syncthreads();
    }

    // --- epilogue ---
#pragma unroll
    for (int mt = 0; mt < 2; ++mt) {
#pragma unroll
        for (int half = 0; half < 2; ++half) {
            const int row = m0 + warp_m * 32 + mt * 16 + (lane >> 2) + half * 8;
#pragma unroll
            for (int nt = 0; nt < 8; ++nt) {
                const int col = n0 + warp_n * 64 + nt * 8 + (lane & 3) * 2;
                float v0 = acc[mt][nt][half * 2 + 0];
                float v1 = acc[mt][nt][half * 2 + 1];
                if (MODE == 0) {
                    *(float2*)&C[(size_t)row * D_MODEL + col] = make_float2(v0, v1);
                } else {
                    const int s  = row & (SEQ - 1);
                    const int b  = row >> 11;
                    const int hh = col >> 7;
                    const int dd = col & (HEAD_DIM - 1);
                    if (MODE == 1) {
                        const float cc = rc[s * 64 + (dd >> 1)];
                        const float sn = rs[s * 64 + (dd >> 1)];
                        const float r1 = (v0 * cc - v1 * sn) * scale;
                        const float r2 = (v0 * sn + v1 * cc) * scale;
                        v0 = r1; v1 = r2;
                    }
                    __half2 h, l;
                    split_h2(v0, v1, h, l);
                    const size_t idx =
                        (((size_t)(b * N_HEADS + hh)) * SEQ + s) * HEAD_DIM + dd;
                    *(__half2*)&OH[idx] = h;
                    *(__half2*)&OL[idx] = l;
                }
            }
        }
    }
}

// ---------------------------------------------------------------------------
// fp16 transpose: [bh][s][d] -> [bh][d][s], hi and lo
// ---------------------------------------------------------------------------
__global__ void mha_t16(const __half* __restrict__ vh, const __half* __restrict__ vl,
                        __half* __restrict__ vth, __half* __restrict__ vtl)
{
    __shared__ __half t[2][32][33];
    const int bh = blockIdx.z;
    const int s0 = blockIdx.x * 32;
    const int d0 = blockIdx.y * 32;
    const int tx = threadIdx.x, ty = threadIdx.y;  // (32, 8)
    const size_t ib = (size_t)bh * SEQ * HEAD_DIM;
#pragma unroll
    for (int i = 0; i < 4; ++i) {
        t[0][ty + 8 * i][tx] = vh[ib + (size_t)(s0 + ty + 8 * i) * HEAD_DIM + d0 + tx];
        t[1][ty + 8 * i][tx] = vl[ib + (size_t)(s0 + ty + 8 * i) * HEAD_DIM + d0 + tx];
    }
    __syncthreads();
    const size_t ob = (size_t)bh * HEAD_DIM * SEQ;
#pragma unroll
    for (int i = 0; i < 4; ++i) {
        const int d = d0 + ty + 8 * i;
        vth[ob + (size_t)d * SEQ + s0 + tx] = t[0][tx][ty + 8 * i];
        vtl[ob + (size_t)d * SEQ + s0 + tx] = t[1][tx][ty + 8 * i];
    }
}

// ---------------------------------------------------------------------------
// Tensor-core causal flash attention (validated R12 core; epilogue now
// writes fp16 hi/lo directly into the final GEMM's A buffers).
// ---------------------------------------------------------------------------
#define FA_SQH 0
#define FA_SQL 16384
#define FA_SKH 32768
#define FA_SKL 49152
#define FA_SVH 65536
#define FA_SVL 81920
#define FA_SMEM 98304

__global__ __launch_bounds__(128, 2)
void mha_flash_mma(const __half* __restrict__ qh, const __half* __restrict__ ql,
                   const __half* __restrict__ kh, const __half* __restrict__ kl,
                   const __half* __restrict__ vth, const __half* __restrict__ vtl,
                   __half* __restrict__ AH, __half* __restrict__ AL)
{
    extern __shared__ char smfa[];
    const uint32_t sb = smem_u32(smfa);
    const int tid  = threadIdx.x;
    const int lane = tid & 31;
    const int w    = tid >> 5;
    const int qb   = blockIdx.x;
    const int bh   = blockIdx.y;
    const int q0   = qb * 64;

    const size_t qoff = ((size_t)bh * SEQ + q0) * HEAD_DIM;
    const __half* Qh = qh + qoff;
    const __half* Ql = ql + qoff;
    const __half* Kb_h = kh + (size_t)bh * SEQ * HEAD_DIM;
    const __half* Kb_l = kl + (size_t)bh * SEQ * HEAD_DIM;
    const __half* Vb_h = vth + (size_t)bh * HEAD_DIM * SEQ;
    const __half* Vb_l = vtl + (size_t)bh * HEAD_DIM * SEQ;

#pragma unroll
    for (int i = 0; i < 8; ++i) {
        const int idx = tid + i * 128;
        const int r = idx >> 4;
        const int c = idx & 15;
        cp16(sb + FA_SQH + qsw(r, c), Qh + (size_t)r * HEAD_DIM + c * 8);
        cp16(sb + FA_SQL + qsw(r, c), Ql + (size_t)r * HEAD_DIM + c * 8);
    }

    float oacc[16][4];
#pragma unroll
    for (int nt = 0; nt < 16; ++nt)
#pragma unroll
        for (int e = 0; e < 4; ++e) oacc[nt][e] = 0.f;
    float m0v = -INFINITY, m1v = -INFINITY, l0v = 0.f, l1v = 0.f;

    for (int kb = 0; kb <= qb; ++kb) {
        const int k0 = kb * 64;
        __syncthreads();
#pragma unroll
        for (int i = 0; i < 8; ++i) {
            const int idx = tid + i * 128;
            const int r = idx >> 4;
            const int c = idx & 15;
            cp16(sb + FA_SKH + qsw(r, c), Kb_h + (size_t)(k0 + r) * HEAD_DIM + c * 8);
            cp16(sb + FA_SKL + qsw(r, c), Kb_l + (size_t)(k0 + r) * HEAD_DIM + c * 8);
            const int rv = idx >> 3;
            const int cv = idx & 7;
            cp16(sb + FA_SVH + vsw(rv, cv), Vb_h + (size_t)rv * SEQ + k0 + cv * 8);
            cp16(sb + FA_SVL + vsw(rv, cv), Vb_l + (size_t)rv * SEQ + k0 + cv * 8);
        }
        CPC();
        CPW(0);
        __syncthreads();

        float sacc[8][4];
#pragma unroll
        for (int nt = 0; nt < 8; ++nt)
#pragma unroll
            for (int e = 0; e < 4; ++e) sacc[nt][e] = 0.f;

#pragma unroll
        for (int ks = 0; ks < 8; ++ks) {
            const int ch = ks * 2 + (lane >> 4);
            uint32_t aqh[4], aql[4];
            {
                const uint32_t so = qsw(16 * w + (lane & 15), ch);
                LDSM4(aqh[0], aqh[1], aqh[2], aqh[3], sb + FA_SQH + so);
                LDSM4(aql[0], aql[1], aql[2], aql[3], sb + FA_SQL + so);
            }
            uint32_t bkh[8][2], bkl[8][2];
#pragma unroll
            for (int nt2 = 0; nt2 < 4; ++nt2) {
                const uint32_t so = qsw(nt2 * 16 + (lane & 15), ch);
                uint32_t t0, t1, t2, t3;
                LDSM4(t0, t1, t2, t3, sb + FA_SKH + so);
                bkh[nt2 * 2][0] = t0; bkh[nt2 * 2][1] = t2;
                bkh[nt2 * 2 + 1][0] = t1; bkh[nt2 * 2 + 1][1] = t3;
                LDSM4(t0, t1, t2, t3, sb + FA_SKL + so);
                bkl[nt2 * 2][0] = t0; bkl[nt2 * 2][1] = t2;
                bkl[nt2 * 2 + 1][0] = t1; bkl[nt2 * 2 + 1][1] = t3;
            }
#pragma unroll
            for (int nt = 0; nt < 8; ++nt) {
                mma16816(sacc[nt], aqh, bkh[nt]);
                mma16816(sacc[nt], aqh, bkl[nt]);
                mma16816(sacc[nt], aql, bkh[nt]);
            }
        }

        const int row0 = q0 + 16 * w + (lane >> 2);
        if (kb == qb) {
#pragma unroll
            for (int nt = 0; nt < 8; ++nt)
#pragma unroll
                for (int e = 0; e < 4; ++e) {
                    const int col = k0 + nt * 8 + (lane & 3) * 2 + (e & 1);
                    const int row = row0 + (e >> 1) * 8;
                    if (col > row) sacc[nt][e] = -INFINITY;
                }
        }

        float rmax0 = -INFINITY, rmax1 = -INFINITY;
#pragma unroll
        for (int nt = 0; nt < 8; ++nt) {
            rmax0 = fmaxf(rmax0, fmaxf(sacc[nt][0], sacc[nt][1]));
            rmax1 = fmaxf(rmax1, fmaxf(sacc[nt][2], sacc[nt][3]));
        }
        rmax0 = fmaxf(rmax0, __shfl_xor_sync(0xffffffffu, rmax0, 1));
        rmax0 = fmaxf(rmax0, __shfl_xor_sync(0xffffffffu, rmax0, 2));
        rmax1 = fmaxf(rmax1, __shfl_xor_sync(0xffffffffu, rmax1, 1));
        rmax1 = fmaxf(rmax1, __shfl_xor_sync(0xffffffffu, rmax1, 2));
        const float mn0 = fmaxf(m0v, rmax0);
        const float mn1 = fmaxf(m1v, rmax1);
        const float al0 = __expf(m0v - mn0);
        const float al1 = __expf(m1v - mn1);
        m0v = mn0; m1v = mn1;
        float rs0 = 0.f, rs1 = 0.f;
#pragma unroll
        for (int nt = 0; nt < 8; ++nt) {
            sacc[nt][0] = __expf(sacc[nt][0] - mn0);
            sacc[nt][1] = __expf(sacc[nt][1] - mn0);
            sacc[nt][2] = __expf(sacc[nt][2] - mn1);
            sacc[nt][3] = __expf(sacc[nt][3] - mn1);
            rs0 += sacc[nt][0] + sacc[nt][1];
            rs1 += sacc[nt][2] + sacc[nt][3];
        }
        rs0 += __shfl_xor_sync(0xffffffffu, rs0, 1);
        rs0 += __shfl_xor_sync(0xffffffffu, rs0, 2);
        rs1 += __shfl_xor_sync(0xffffffffu, rs1, 1);
        rs1 += __shfl_xor_sync(0xffffffffu, rs1, 2);
        l0v = l0v * al0 + rs0;
        l1v = l1v * al1 + rs1;
#pragma unroll
        for (int nt = 0; nt < 16; ++nt) {
            oacc[nt][0] *= al0; oacc[nt][1] *= al0;
            oacc[nt][2] *= al1; oacc[nt][3] *= al1;
        }

        uint32_t pfh[4][4], pfl[4][4];
#pragma unroll
        for (int kc = 0; kc < 4; ++kc) {
#pragma unroll
            for (int e = 0; e < 4; ++e) {
                const int t  = 2 * kc + (e >> 1);
                const int e0 = (e & 1) * 2;
                __half2 hv, lv;
                split_h2(sacc[t][e0], sacc[t][e0 + 1], hv, lv);
                const int slot = ((e >> 1) << 1) | (e & 1);
                pfh[kc][slot] = *(uint32_t*)&hv;
                pfl[kc][slot] = *(uint32_t*)&lv;
            }
        }

#pragma unroll
        for (int kc = 0; kc < 4; ++kc) {
#pragma unroll
            for (int g = 0; g < 8; ++g) {
                const uint32_t so = vsw(g * 16 + (lane & 15), kc * 2 + (lane >> 4));
                uint32_t t0, t1, t2, t3;
                uint32_t b0h[2], b1h[2], b0l[2], b1l[2];
                LDSM4(t0, t1, t2, t3, sb + FA_SVH + so);
                b0h[0] = t0; b0h[1] = t2; b1h[0] = t1; b1h[1] = t3;
                LDSM4(t0, t1, t2, t3, sb + FA_SVL + so);
                b0l[0] = t0; b0l[1] = t2; b1l[0] = t1; b1l[1] = t3;
                mma16816(oacc[2 * g],     pfh[kc], b0h);
                mma16816(oacc[2 * g],     pfh[kc], b0l);
                mma16816(oacc[2 * g],     pfl[kc], b0h);
                mma16816(oacc[2 * g + 1], pfh[kc], b1h);
                mma16816(oacc[2 * g + 1], pfh[kc], b1l);
                mma16816(oacc[2 * g + 1], pfl[kc], b1h);
            }
        }
    }

    const float inv0 = 1.0f / l0v;
    const float inv1 = 1.0f / l1v;
    const int b = bh >> 4;
    const int h = bh & 15;
    const int row0 = q0 + 16 * w + (lane >> 2);
#pragma unroll
    for (int nt = 0; nt < 16; ++nt) {
        const int col = h * HEAD_DIM + nt * 8 + (lane & 3) * 2;
        const size_t i0 = ((size_t)(b * SEQ + row0)) * D_MODEL + col;
        const size_t i1 = ((size_t)(b * SEQ + row0 + 8)) * D_MODEL + col;
        __half2 h0, l0, h1, l1;
        split_h2(oacc[nt][0] * inv0, oacc[nt][1] * inv0, h0, l0);
        split_h2(oacc[nt][2] * inv1, oacc[nt][3] * inv1, h1, l1);
        *(__half2*)&AH[i0] = h0;
        *(__half2*)&AL[i0] = l0;
        *(__half2*)&AH[i1] = h1;
        *(__half2*)&AL[i1] = l1;
    }
}

// ---------------------------------------------------------------------------
// Launch
// ---------------------------------------------------------------------------
extern "C" void kernel_launch(void* const* d_in, const int* in_sizes, int n_in,
                              void* d_out, int out_size)
{
    (void)in_sizes; (void)n_in; (void)out_size;
    const float* x  = (const float*)d_in[0];
    const float* wq = (const float*)d_in[1];
    const float* wk = (const float*)d_in[2];
    const float* wv = (const float*)d_in[3];
    const float* wo = (const float*)d_in[4];
    float* out = (float*)d_out;

    __half *xh, *xl, *ah, *al, *wqh, *wkh, *wvh, *woh;
    cudaGetSymbolAddress((void**)&xh, g_x_hi);
    cudaGetSymbolAddress((void**)&xl, g_x_lo);
    cudaGetSymbolAddress((void**)&ah, g_a_hi);
    cudaGetSymbolAddress((void**)&al, g_a_lo);
    cudaGetSymbolAddress((void**)&wqh, g_wq_h);
    cudaGetSymbolAddress((void**)&wkh, g_wk_h);
    cudaGetSymbolAddress((void**)&wvh, g_wv_h);
    cudaGetSymbolAddress((void**)&woh, g_wo_h);

    __half *q16h, *q16l, *k16h, *k16l, *v16h, *v16l, *vt16h, *vt16l;
    cudaGetSymbolAddress((void**)&q16h, g_q16h);
    cudaGetSymbolAddress((void**)&q16l, g_q16l);
    cudaGetSymbolAddress((void**)&k16h, g_k16h);
    cudaGetSymbolAddress((void**)&k16l, g_k16l);
    cudaGetSymbolAddress((void**)&v16h, g_v16h);
    cudaGetSymbolAddress((void**)&v16l, g_v16l);
    cudaGetSymbolAddress((void**)&vt16h, g_vt16h);
    cudaGetSymbolAddress((void**)&vt16l, g_vt16l);

    float *rc, *rs;
    cudaGetSymbolAddress((void**)&rc, g_ropec);
    cudaGetSymbolAddress((void**)&rs, g_ropes);

    const int nx4 = M_ROWS * D_MODEL / 4;
    const int nw4 = D_MODEL * D_MODEL / 4;

    mha_split16<<<nx4 / 256, 256>>>(x, xh, xl, nx4);
    mha_cvt16<<<nw4 / 256, 256>>>(wq, wqh, nw4);
    mha_cvt16<<<nw4 / 256, 256>>>(wk, wkh, nw4);
    mha_cvt16<<<nw4 / 256, 256>>>(wv, wvh, nw4);
    mha_cvt16<<<nw4 / 256, 256>>>(wo, woh, nw4);
    mha_rope_tables<<<SEQ, 64>>>(rc, rs);

    cudaFuncSetAttribute(gemm_t<0, 2>, cudaFuncAttributeMaxDynamicSharedMemorySize,
                         GSMEM);
    cudaFuncSetAttribute(gemm_t<1, 2>, cudaFuncAttributeMaxDynamicSharedMemorySize,
                         GSMEM);
    cudaFuncSetAttribute(gemm_t<2, 1>, cudaFuncAttributeMaxDynamicSharedMemorySize,
                         GSMEM);
    const dim3 gg(D_MODEL / 128, M_ROWS / 128);

    gemm_t<1, 2><<<gg, 256, GSMEM>>>(xh, xl, wqh, nullptr, q16h, q16l,
                                     0.08838834764831845f, rc, rs);
    gemm_t<1, 2><<<gg, 256, GSMEM>>>(xh, xl, wkh, nullptr, k16h, k16l,
                                     1.0f, rc, rs);
    gemm_t<2, 1><<<gg, 256, GSMEM>>>(xh, nullptr, wvh, nullptr, v16h, v16l,
                                     1.0f, rc, rs);

    mha_t16<<<dim3(SEQ / 32, HEAD_DIM / 32, BH), dim3(32, 8)>>>(v16h, v16l,
                                                                vt16h, vt16l);

    cudaFuncSetAttribute(mha_flash_mma, cudaFuncAttributeMaxDynamicSharedMemorySize,
                         FA_SMEM);
    mha_flash_mma<<<dim3(SEQ / 64, BH), 128, FA_SMEM>>>(q16h, q16l, k16h, k16l,
                                                        vt16h, vt16l, ah, al);

    gemm_t<0, 2><<<gg, 256, GSMEM>>>(ah, al, woh, out, nullptr, nullptr,
                                     1.0f, rc, rs);
}

// round 14
// speedup vs baseline: 4.5947x; 1.2481x over previous
#include <cuda_runtime.h>
#include <cuda_fp16.h>
#include <cstdint>
#include <math.h>

#define D_MODEL 2048
#define N_HEADS 16
#define HEAD_DIM 128
#define SEQ 2048
#define BATCH 2
#define M_ROWS (BATCH * SEQ)
#define BH (BATCH * N_HEADS)

// ---------------------------------------------------------------------------
// Scratch (static device arrays; no allocation at kernel_launch time)
// ---------------------------------------------------------------------------
__device__ __half g_x_hi[(size_t)M_ROWS * D_MODEL];
__device__ __half g_x_lo[(size_t)M_ROWS * D_MODEL];
__device__ __half g_a_hi[(size_t)M_ROWS * D_MODEL];
__device__ __half g_wq_h[(size_t)D_MODEL * D_MODEL];
__device__ __half g_wk_h[(size_t)D_MODEL * D_MODEL];
__device__ __half g_wv_h[(size_t)D_MODEL * D_MODEL];
__device__ __half g_wo_h[(size_t)D_MODEL * D_MODEL];
__device__ __half g_q16h[(size_t)BH * SEQ * HEAD_DIM];
__device__ __half g_q16l[(size_t)BH * SEQ * HEAD_DIM];
__device__ __half g_k16h[(size_t)BH * SEQ * HEAD_DIM];
__device__ __half g_k16l[(size_t)BH * SEQ * HEAD_DIM];
__device__ __half g_v16h[(size_t)BH * SEQ * HEAD_DIM];
__device__ __half g_vt16h[(size_t)BH * HEAD_DIM * SEQ];
__device__ float g_ropec[SEQ * 64];
__device__ float g_ropes[SEQ * 64];

// ---------------------------------------------------------------------------
// primitives
// ---------------------------------------------------------------------------
__device__ __forceinline__ uint32_t smem_u32(const void* p) {
    uint32_t a;
    asm("{ .reg .u64 t; cvta.to.shared.u64 t, %1; cvt.u32.u64 %0, t; }"
        : "=r"(a) : "l"(p));
    return a;
}
__device__ __forceinline__ void cp16(uint32_t s, const void* g) {
    asm volatile("cp.async.cg.shared.global [%0], [%1], 16;"
                 :: "r"(s), "l"(__cvta_generic_to_global(g)) : "memory");
}
#define CPC() asm volatile("cp.async.commit_group;" ::: "memory")
#define CPW(N) asm volatile("cp.async.wait_group %0;" :: "n"(N) : "memory")

#define LDSM4(r0, r1, r2, r3, addr)                                            \
    asm volatile("ldmatrix.sync.aligned.m8n8.x4.shared.b16 {%0,%1,%2,%3}, [%4];" \
                 : "=r"(r0), "=r"(r1), "=r"(r2), "=r"(r3) : "r"(addr))

__device__ __forceinline__ void mma16816(float* d, const uint32_t* a,
                                         const uint32_t* b) {
    asm volatile(
        "mma.sync.aligned.m16n8k16.row.col.f32.f16.f16.f32 "
        "{%0,%1,%2,%3}, {%4,%5,%6,%7}, {%8,%9}, {%0,%1,%2,%3};"
        : "+f"(d[0]), "+f"(d[1]), "+f"(d[2]), "+f"(d[3])
        : "r"(a[0]), "r"(a[1]), "r"(a[2]), "r"(a[3]), "r"(b[0]), "r"(b[1]));
}

// swizzles
__device__ __forceinline__ uint32_t g128(int r, int c) {  // r<128, c<8
    return (uint32_t)((r << 7) + ((c ^ (r & 7)) << 4));
}
__device__ __forceinline__ uint32_t qsw(int r, int c) {   // r<64, c<16
    return (uint32_t)((r << 8) + ((c ^ (r & 7)) << 4));
}
__device__ __forceinline__ uint32_t vsw(int r, int c) {   // r<128, c<8
    return (uint32_t)((r << 7) + ((c ^ (r & 7)) << 4));
}

__device__ __forceinline__ void split_h2(float a, float b, __half2& h, __half2& l)
{
    const __half h0 = __float2half(a), h1 = __float2half(b);
    h = __halves2half2(h0, h1);
    l = __halves2half2(__float2half(a - __half2float(h0)),
                       __float2half(b - __half2float(h1)));
}

// ---------------------------------------------------------------------------
// converts + RoPE tables
// ---------------------------------------------------------------------------
__global__ void mha_split16(const float* __restrict__ src,
                            __half* __restrict__ hi,
                            __half* __restrict__ lo, int n4)
{
    int i = blockIdx.x * blockDim.x + threadIdx.x;
    if (i >= n4) return;
    float4 v = ((const float4*)src)[i];
    __half2 h0, l0, h1, l1;
    split_h2(v.x, v.y, h0, l0);
    split_h2(v.z, v.w, h1, l1);
    ((__half2*)hi)[i * 2 + 0] = h0;
    ((__half2*)hi)[i * 2 + 1] = h1;
    ((__half2*)lo)[i * 2 + 0] = l0;
    ((__half2*)lo)[i * 2 + 1] = l1;
}

__global__ void mha_cvt16(const float* __restrict__ src,
                          __half* __restrict__ dst, int n4)
{
    int i = blockIdx.x * blockDim.x + threadIdx.x;
    if (i >= n4) return;
    float4 v = ((const float4*)src)[i];
    __half2* D = (__half2*)dst;
    D[i * 2 + 0] = __floats2half2_rn(v.x, v.y);
    D[i * 2 + 1] = __floats2half2_rn(v.z, v.w);
}

__global__ void mha_rope_tables(float* __restrict__ rc, float* __restrict__ rs)
{
    const int s = blockIdx.x;
    const int i = threadIdx.x;  // 0..63
    const int jc = (2 * i) & 63;
    const int js = (2 * i + 1) & 63;
    const float invc = powf(10000.0f, -(float)jc * (1.0f / 64.0f));
    const float invs = powf(10000.0f, -(float)js * (1.0f / 64.0f));
    rc[s * 64 + i] = cosf((float)s * invc);
    rs[s * 64 + i] = sinf((float)s * invs);
}

// ---------------------------------------------------------------------------
// Templated GEMM: C[m,n] = sum_k A[m,k]*B[n,k]. Tile 128x128, K-chunk 64,
// 256 thr (8 warps 4m x 2n), double-buffered cp.async.
// NPASS: 2 = (A_hi+A_lo)@B, 1 = A_hi@B.
// MODE: 0 = fp32 row-major out; 1 = RoPE+scale, fp16 hi/lo scatter (dual
//       launch: blockIdx.x>=16 uses B2/OH2/OL2/scale2); 2 = fp16 hi scatter.
// ---------------------------------------------------------------------------
#define GSTAGE 49152
#define GSMEM  (2 * GSTAGE)

template <int MODE, int NPASS>
__global__ __launch_bounds__(256, 2)
void gemm_t(const __half* __restrict__ Ahi, const __half* __restrict__ Alo,
            const __half* __restrict__ Bh, float* __restrict__ C,
            __half* __restrict__ OH, __half* __restrict__ OL, float scale,
            const float* __restrict__ rc, const float* __restrict__ rs,
            const __half* __restrict__ B2, __half* __restrict__ OH2,
            __half* __restrict__ OL2, float scale2)
{
    extern __shared__ char smg[];
    const uint32_t sbase = smem_u32(smg);
    const int K = D_MODEL;
    const int tid  = threadIdx.x;
    const int lane = tid & 31;
    const int wid  = tid >> 5;
    const int warp_m = wid & 3;
    const int warp_n = wid >> 2;
    const int m0 = blockIdx.y * 128;

    const __half* Bsel = Bh;
    __half* OHs = OH;
    __half* OLs = OL;
    float scl = scale;
    int nblk = blockIdx.x;
    if (MODE == 1 && nblk >= 16) {
        Bsel = B2; OHs = OH2; OLs = OL2; scl = scale2; nblk -= 16;
    }
    const int n0 = nblk * 128;

    float acc[2][8][4];
#pragma unroll
    for (int mt = 0; mt < 2; ++mt)
#pragma unroll
        for (int nt = 0; nt < 8; ++nt)
#pragma unroll
            for (int e = 0; e < 4; ++e) acc[mt][nt][e] = 0.f;

    auto load_chunk = [&](int kc, int s) {
        const uint32_t st = sbase + s * GSTAGE;
#pragma unroll
        for (int i = 0; i < 4; ++i) {
            const int idx = tid + i * 256;
            const int r = idx >> 3;
            const int c = idx & 7;
            const uint32_t so = g128(r, c);
            const size_t ga = (size_t)(m0 + r) * K + kc + c * 8;
            const size_t gb = (size_t)(n0 + r) * K + kc + c * 8;
            cp16(st + so, Ahi + ga);
            if (NPASS == 2) cp16(st + 16384 + so, Alo + ga);
            cp16(st + 32768 + so, Bsel + gb);
        }
    };

    load_chunk(0, 0);
    CPC();

    const int nchunks = K / 64;
    for (int c = 0; c < nchunks; ++c) {
        const int buf = c & 1;
        if (c + 1 < nchunks) {
            load_chunk((c + 1) * 64, buf ^ 1);
            CPC();
            CPW(1);
        } else {
            CPW(0);
        }
        __syncthreads();

        const uint32_t ab_hi = sbase + buf * GSTAGE;
        const uint32_t ab_lo = ab_hi + 16384;
        const uint32_t bb_hi = ab_hi + 32768;

#pragma unroll
        for (int ks = 0; ks < 4; ++ks) {
            const int ch = ks * 2 + (lane >> 4);
            uint32_t ah[2][4], al[2][4];
#pragma unroll
            for (int mt = 0; mt < 2; ++mt) {
                const int r = warp_m * 32 + mt * 16 + (lane & 15);
                const uint32_t so = g128(r, ch);
                LDSM4(ah[mt][0], ah[mt][1], ah[mt][2], ah[mt][3], ab_hi + so);
                if (NPASS == 2)
                    LDSM4(al[mt][0], al[mt][1], al[mt][2], al[mt][3], ab_lo + so);
            }
            uint32_t bh[8][2];
#pragma unroll
            for (int nt2 = 0; nt2 < 4; ++nt2) {
                const int r = warp_n * 64 + nt2 * 16 + (lane & 15);
                const uint32_t so = g128(r, ch);
                uint32_t t0, t1, t2, t3;
                LDSM4(t0, t1, t2, t3, bb_hi + so);
                bh[nt2 * 2][0] = t0; bh[nt2 * 2][1] = t2;
                bh[nt2 * 2 + 1][0] = t1; bh[nt2 * 2 + 1][1] = t3;
            }
#pragma unroll
            for (int nt = 0; nt < 8; ++nt)
#pragma unroll
                for (int mt = 0; mt < 2; ++mt)
                    mma16816(acc[mt][nt], ah[mt], bh[nt]);
            if (NPASS == 2) {
#pragma unroll
                for (int nt = 0; nt < 8; ++nt)
#pragma unroll
                    for (int mt = 0; mt < 2; ++mt)
                        mma16816(acc[mt][nt], al[mt], bh[nt]);
            }
        }
        __syncthreads();
    }

    // --- epilogue ---
#pragma unroll
    for (int mt = 0; mt < 2; ++mt) {
#pragma unroll
        for (int half = 0; half < 2; ++half) {
            const int row = m0 + warp_m * 32 + mt * 16 + (lane >> 2) + half * 8;
#pragma unroll
            for (int nt = 0; nt < 8; ++nt) {
                const int col = n0 + warp_n * 64 + nt * 8 + (lane & 3) * 2;
                float v0 = acc[mt][nt][half * 2 + 0];
                float v1 = acc[mt][nt][half * 2 + 1];
                if (MODE == 0) {
                    *(float2*)&C[(size_t)row * D_MODEL + col] = make_float2(v0, v1);
                } else {
                    const int s  = row & (SEQ - 1);
                    const int b  = row >> 11;
                    const int hh = col >> 7;
                    const int dd = col & (HEAD_DIM - 1);
                    const size_t idx =
                        (((size_t)(b * N_HEADS + hh)) * SEQ + s) * HEAD_DIM + dd;
                    if (MODE == 1) {
                        const float cc = rc[s * 64 + (dd >> 1)];
                        const float sn = rs[s * 64 + (dd >> 1)];
                        const float r1 = (v0 * cc - v1 * sn) * scl;
                        const float r2 = (v0 * sn + v1 * cc) * scl;
                        __half2 h, l;
                        split_h2(r1, r2, h, l);
                        *(__half2*)&OHs[idx] = h;
                        *(__half2*)&OLs[idx] = l;
                    } else {  // MODE == 2: hi only
                        *(__half2*)&OHs[idx] = __floats2half2_rn(v0, v1);
                    }
                }
            }
        }
    }
}

// ---------------------------------------------------------------------------
// fp16 transpose (hi only): [bh][s][d] -> [bh][d][s]
// ---------------------------------------------------------------------------
__global__ void mha_t16(const __half* __restrict__ vh, __half* __restrict__ vth)
{
    __shared__ __half t[32][33];
    const int bh = blockIdx.z;
    const int s0 = blockIdx.x * 32;
    const int d0 = blockIdx.y * 32;
    const int tx = threadIdx.x, ty = threadIdx.y;  // (32, 8)
    const size_t ib = (size_t)bh * SEQ * HEAD_DIM;
#pragma unroll
    for (int i = 0; i < 4; ++i)
        t[ty + 8 * i][tx] = vh[ib + (size_t)(s0 + ty + 8 * i) * HEAD_DIM + d0 + tx];
    __syncthreads();
    const size_t ob = (size_t)bh * HEAD_DIM * SEQ;
#pragma unroll
    for (int i = 0; i < 4; ++i) {
        const int d = d0 + ty + 8 * i;
        vth[ob + (size_t)d * SEQ + s0 + tx] = t[tx][ty + 8 * i];
    }
}

// ---------------------------------------------------------------------------
// Tensor-core causal flash attention. QK^T 3-pass (logit path), PV 2-pass
// (P hi/lo x V hi; V linear path). Writes fp16 hi only for the out GEMM.
// ---------------------------------------------------------------------------
#define FA_SQH 0
#define FA_SQL 16384
#define FA_SKH 32768
#define FA_SKL 49152
#define FA_SVH 65536
#define FA_SMEM 81920

__global__ __launch_bounds__(128, 2)
void mha_flash_mma(const __half* __restrict__ qh, const __half* __restrict__ ql,
                   const __half* __restrict__ kh, const __half* __restrict__ kl,
                   const __half* __restrict__ vth, __half* __restrict__ AH)
{
    extern __shared__ char smfa[];
    const uint32_t sb = smem_u32(smfa);
    const int tid  = threadIdx.x;
    const int lane = tid & 31;
    const int w    = tid >> 5;
    const int qb   = blockIdx.x;
    const int bh   = blockIdx.y;
    const int q0   = qb * 64;

    const size_t qoff = ((size_t)bh * SEQ + q0) * HEAD_DIM;
    const __half* Qh = qh + qoff;
    const __half* Ql = ql + qoff;
    const __half* Kb_h = kh + (size_t)bh * SEQ * HEAD_DIM;
    const __half* Kb_l = kl + (size_t)bh * SEQ * HEAD_DIM;
    const __half* Vb_h = vth + (size_t)bh * HEAD_DIM * SEQ;

#pragma unroll
    for (int i = 0; i < 8; ++i) {
        const int idx = tid + i * 128;
        const int r = idx >> 4;
        const int c = idx & 15;
        cp16(sb + FA_SQH + qsw(r, c), Qh + (size_t)r * HEAD_DIM + c * 8);
        cp16(sb + FA_SQL + qsw(r, c), Ql + (size_t)r * HEAD_DIM + c * 8);
    }

    float oacc[16][4];
#pragma unroll
    for (int nt = 0; nt < 16; ++nt)
#pragma unroll
        for (int e = 0; e < 4; ++e) oacc[nt][e] = 0.f;
    float m0v = -INFINITY, m1v = -INFINITY, l0v = 0.f, l1v = 0.f;

    for (int kb = 0; kb <= qb; ++kb) {
        const int k0 = kb * 64;
        __syncthreads();
#pragma unroll
        for (int i = 0; i < 8; ++i) {
            const int idx = tid + i * 128;
            const int r = idx >> 4;
            const int c = idx & 15;
            cp16(sb + FA_SKH + qsw(r, c), Kb_h + (size_t)(k0 + r) * HEAD_DIM + c * 8);
            cp16(sb + FA_SKL + qsw(r, c), Kb_l + (size_t)(k0 + r) * HEAD_DIM + c * 8);
            const int rv = idx >> 3;
            const int cv = idx & 7;
            cp16(sb + FA_SVH + vsw(rv, cv), Vb_h + (size_t)rv * SEQ + k0 + cv * 8);
        }
        CPC();
        CPW(0);
        __syncthreads();

        float sacc[8][4];
#pragma unroll
        for (int nt = 0; nt < 8; ++nt)
#pragma unroll
            for (int e = 0; e < 4; ++e) sacc[nt][e] = 0.f;

#pragma unroll
        for (int ks = 0; ks < 8; ++ks) {
            const int ch = ks * 2 + (lane >> 4);
            uint32_t aqh[4], aql[4];
            {
                const uint32_t so = qsw(16 * w + (lane & 15), ch);
                LDSM4(aqh[0], aqh[1], aqh[2], aqh[3], sb + FA_SQH + so);
                LDSM4(aql[0], aql[1], aql[2], aql[3], sb + FA_SQL + so);
            }
            uint32_t bkh[8][2], bkl[8][2];
#pragma unroll
            for (int nt2 = 0; nt2 < 4; ++nt2) {
                const uint32_t so = qsw(nt2 * 16 + (lane & 15), ch);
                uint32_t t0, t1, t2, t3;
                LDSM4(t0, t1, t2, t3, sb + FA_SKH + so);
                bkh[nt2 * 2][0] = t0; bkh[nt2 * 2][1] = t2;
                bkh[nt2 * 2 + 1][0] = t1; bkh[nt2 * 2 + 1][1] = t3;
                LDSM4(t0, t1, t2, t3, sb + FA_SKL + so);
                bkl[nt2 * 2][0] = t0; bkl[nt2 * 2][1] = t2;
                bkl[nt2 * 2 + 1][0] = t1; bkl[nt2 * 2 + 1][1] = t3;
            }
#pragma unroll
            for (int nt = 0; nt < 8; ++nt) {
                mma16816(sacc[nt], aqh, bkh[nt]);
                mma16816(sacc[nt], aqh, bkl[nt]);
                mma16816(sacc[nt], aql, bkh[nt]);
            }
        }

        const int row0 = q0 + 16 * w + (lane >> 2);
        if (kb == qb) {
#pragma unroll
            for (int nt = 0; nt < 8; ++nt)
#pragma unroll
                for (int e = 0; e < 4; ++e) {
                    const int col = k0 + nt * 8 + (lane & 3) * 2 + (e & 1);
                    const int row = row0 + (e >> 1) * 8;
                    if (col > row) sacc[nt][e] = -INFINITY;
                }
        }

        float rmax0 = -INFINITY, rmax1 = -INFINITY;
#pragma unroll
        for (int nt = 0; nt < 8; ++nt) {
            rmax0 = fmaxf(rmax0, fmaxf(sacc[nt][0], sacc[nt][1]));
            rmax1 = fmaxf(rmax1, fmaxf(sacc[nt][2], sacc[nt][3]));
        }
        rmax0 = fmaxf(rmax0, __shfl_xor_sync(0xffffffffu, rmax0, 1));
        rmax0 = fmaxf(rmax0, __shfl_xor_sync(0xffffffffu, rmax0, 2));
        rmax1 = fmaxf(rmax1, __shfl_xor_sync(0xffffffffu, rmax1, 1));
        rmax1 = fmaxf(rmax1, __shfl_xor_sync(0xffffffffu, rmax1, 2));
        const float mn0 = fmaxf(m0v, rmax0);
        const float mn1 = fmaxf(m1v, rmax1);
        const float al0 = __expf(m0v - mn0);
        const float al1 = __expf(m1v - mn1);
        m0v = mn0; m1v = mn1;
        float rs0 = 0.f, rs1 = 0.f;
#pragma unroll
        for (int nt = 0; nt < 8; ++nt) {
            sacc[nt][0] = __expf(sacc[nt][0] - mn0);
            sacc[nt][1] = __expf(sacc[nt][1] - mn0);
            sacc[nt][2] = __expf(sacc[nt][2] - mn1);
            sacc[nt][3] = __expf(sacc[nt][3] - mn1);
            rs0 += sacc[nt][0] + sacc[nt][1];
            rs1 += sacc[nt][2] + sacc[nt][3];
        }
        rs0 += __shfl_xor_sync(0xffffffffu, rs0, 1);
        rs0 += __shfl_xor_sync(0xffffffffu, rs0, 2);
        rs1 += __shfl_xor_sync(0xffffffffu, rs1, 1);
        rs1 += __shfl_xor_sync(0xffffffffu, rs1, 2);
        l0v = l0v * al0 + rs0;
        l1v = l1v * al1 + rs1;
#pragma unroll
        for (int nt = 0; nt < 16; ++nt) {
            oacc[nt][0] *= al0; oacc[nt][1] *= al0;
            oacc[nt][2] *= al1; oacc[nt][3] *= al1;
        }

        uint32_t pfh[4][4], pfl[4][4];
#pragma unroll
        for (int kc = 0; kc < 4; ++kc) {
#pragma unroll
            for (int e = 0; e < 4; ++e) {
                const int t  = 2 * kc + (e >> 1);
                const int e0 = (e & 1) * 2;
                __half2 hv, lv;
                split_h2(sacc[t][e0], sacc[t][e0 + 1], hv, lv);
                const int slot = ((e >> 1) << 1) | (e & 1);
                pfh[kc][slot] = *(uint32_t*)&hv;
                pfl[kc][slot] = *(uint32_t*)&lv;
            }
        }

#pragma unroll
        for (int kc = 0; kc < 4; ++kc) {
#pragma unroll
            for (int g = 0; g < 8; ++g) {
                const uint32_t so = vsw(g * 16 + (lane & 15), kc * 2 + (lane >> 4));
                uint32_t t0, t1, t2, t3;
                uint32_t b0h[2], b1h[2];
                LDSM4(t0, t1, t2, t3, sb + FA_SVH + so);
                b0h[0] = t0; b0h[1] = t2; b1h[0] = t1; b1h[1] = t3;
                mma16816(oacc[2 * g],     pfh[kc], b0h);
                mma16816(oacc[2 * g],     pfl[kc], b0h);
                mma16816(oacc[2 * g + 1], pfh[kc], b1h);
                mma16816(oacc[2 * g + 1], pfl[kc], b1h);
            }
        }
    }

    const float inv0 = 1.0f / l0v;
    const float inv1 = 1.0f / l1v;
    const int b = bh >> 4;
    const int h = bh & 15;
    const int row0 = q0 + 16 * w + (lane >> 2);
#pragma unroll
    for (int nt = 0; nt < 16; ++nt) {
        const int col = h * HEAD_DIM + nt * 8 + (lane & 3) * 2;
        const size_t i0 = ((size_t)(b * SEQ + row0)) * D_MODEL + col;
        const size_t i1 = ((size_t)(b * SEQ + row0 + 8)) * D_MODEL + col;
        *(__half2*)&AH[i0] = __floats2half2_rn(oacc[nt][0] * inv0,
                                               oacc[nt][1] * inv0);
        *(__half2*)&AH[i1] = __floats2half2_rn(oacc[nt][2] * inv1,
                                               oacc[nt][3] * inv1);
    }
}

// ---------------------------------------------------------------------------
// Launch
// ---------------------------------------------------------------------------
extern "C" void kernel_launch(void* const* d_in, const int* in_sizes, int n_in,
                              void* d_out, int out_size)
{
    (void)in_sizes; (void)n_in; (void)out_size;
    const float* x  = (const float*)d_in[0];
    const float* wq = (const float*)d_in[1];
    const float* wk = (const float*)d_in[2];
    const float* wv = (const float*)d_in[3];
    const float* wo = (const float*)d_in[4];
    float* out = (float*)d_out;

    __half *xh, *xl, *ah, *wqh, *wkh, *wvh, *woh;
    cudaGetSymbolAddress((void**)&xh, g_x_hi);
    cudaGetSymbolAddress((void**)&xl, g_x_lo);
    cudaGetSymbolAddress((void**)&ah, g_a_hi);
    cudaGetSymbolAddress((void**)&wqh, g_wq_h);
    cudaGetSymbolAddress((void**)&wkh, g_wk_h);
    cudaGetSymbolAddress((void**)&wvh, g_wv_h);
    cudaGetSymbolAddress((void**)&woh, g_wo_h);

    __half *q16h, *q16l, *k16h, *k16l, *v16h, *vt16h;
    cudaGetSymbolAddress((void**)&q16h, g_q16h);
    cudaGetSymbolAddress((void**)&q16l, g_q16l);
    cudaGetSymbolAddress((void**)&k16h, g_k16h);
    cudaGetSymbolAddress((void**)&k16l, g_k16l);
    cudaGetSymbolAddress((void**)&v16h, g_v16h);
    cudaGetSymbolAddress((void**)&vt16h, g_vt16h);

    float *rc, *rs;
    cudaGetSymbolAddress((void**)&rc, g_ropec);
    cudaGetSymbolAddress((void**)&rs, g_ropes);

    const int nx4 = M_ROWS * D_MODEL / 4;
    const int nw4 = D_MODEL * D_MODEL / 4;

    mha_split16<<<nx4 / 256, 256>>>(x, xh, xl, nx4);
    mha_cvt16<<<nw4 / 256, 256>>>(wq, wqh, nw4);
    mha_cvt16<<<nw4 / 256, 256>>>(wk, wkh, nw4);
    mha_cvt16<<<nw4 / 256, 256>>>(wv, wvh, nw4);
    mha_cvt16<<<nw4 / 256, 256>>>(wo, woh, nw4);
    mha_rope_tables<<<SEQ, 64>>>(rc, rs);

    cudaFuncSetAttribute(gemm_t<0, 1>, cudaFuncAttributeMaxDynamicSharedMemorySize,
                         GSMEM);
    cudaFuncSetAttribute(gemm_t<1, 2>, cudaFuncAttributeMaxDynamicSharedMemorySize,
                         GSMEM);
    cudaFuncSetAttribute(gemm_t<2, 1>, cudaFuncAttributeMaxDynamicSharedMemorySize,
                         GSMEM);
    const dim3 gg(D_MODEL / 128, M_ROWS / 128);

    // Q and K in one launch (blockIdx.x>=16 -> K side)
    gemm_t<1, 2><<<dim3(32, M_ROWS / 128), 256, GSMEM>>>(
        xh, xl, wqh, nullptr, q16h, q16l, 0.08838834764831845f, rc, rs,
        wkh, k16h, k16l, 1.0f);
    gemm_t<2, 1><<<gg, 256, GSMEM>>>(xh, nullptr, wvh, nullptr, v16h, nullptr,
                                     1.0f, rc, rs, nullptr, nullptr, nullptr, 0.f);

    mha_t16<<<dim3(SEQ / 32, HEAD_DIM / 32, BH), dim3(32, 8)>>>(v16h, vt16h);

    cudaFuncSetAttribute(mha_flash_mma, cudaFuncAttributeMaxDynamicSharedMemorySize,
                         FA_SMEM);
    mha_flash_mma<<<dim3(SEQ / 64, BH), 128, FA_SMEM>>>(q16h, q16l, k16h, k16l,
                                                        vt16h, ah);

    gemm_t<0, 1><<<gg, 256, GSMEM>>>(ah, nullptr, woh, out, nullptr, nullptr,
                                     1.0f, rc, rs, nullptr, nullptr, nullptr, 0.f);
}

// round 15
// speedup vs baseline: 4.8008x; 1.0448x over previous
#include <cuda_runtime.h>
#include <cuda_fp16.h>
#include <cstdint>
#include <math.h>

#define D_MODEL 2048
#define N_HEADS 16
#define HEAD_DIM 128
#define SEQ 2048
#define BATCH 2
#define M_ROWS (BATCH * SEQ)
#define BH (BATCH * N_HEADS)

// ---------------------------------------------------------------------------
// Scratch (static device arrays; no allocation at kernel_launch time)
// ---------------------------------------------------------------------------
__device__ __half g_x_hi[(size_t)M_ROWS * D_MODEL];
__device__ __half g_x_lo[(size_t)M_ROWS * D_MODEL];
__device__ __half g_a_hi[(size_t)M_ROWS * D_MODEL];
__device__ __half g_wq_h[(size_t)D_MODEL * D_MODEL];
__device__ __half g_wk_h[(size_t)D_MODEL * D_MODEL];
__device__ __half g_wv_h[(size_t)D_MODEL * D_MODEL];
__device__ __half g_wo_h[(size_t)D_MODEL * D_MODEL];
__device__ __half g_q16h[(size_t)BH * SEQ * HEAD_DIM];
__device__ __half g_q16l[(size_t)BH * SEQ * HEAD_DIM];
__device__ __half g_k16h[(size_t)BH * SEQ * HEAD_DIM];
__device__ __half g_k16l[(size_t)BH * SEQ * HEAD_DIM];
__device__ __half g_v16h[(size_t)BH * SEQ * HEAD_DIM];
__device__ __half g_vt16h[(size_t)BH * HEAD_DIM * SEQ];
__device__ float g_ropec[SEQ * 64];
__device__ float g_ropes[SEQ * 64];

// ---------------------------------------------------------------------------
// primitives
// ---------------------------------------------------------------------------
__device__ __forceinline__ uint32_t smem_u32(const void* p) {
    uint32_t a;
    asm("{ .reg .u64 t; cvta.to.shared.u64 t, %1; cvt.u32.u64 %0, t; }"
        : "=r"(a) : "l"(p));
    return a;
}
__device__ __forceinline__ void cp16(uint32_t s, const void* g) {
    asm volatile("cp.async.cg.shared.global [%0], [%1], 16;"
                 :: "r"(s), "l"(__cvta_generic_to_global(g)) : "memory");
}
#define CPC() asm volatile("cp.async.commit_group;" ::: "memory")
#define CPW(N) asm volatile("cp.async.wait_group %0;" :: "n"(N) : "memory")

#define LDSM4(r0, r1, r2, r3, addr)                                            \
    asm volatile("ldmatrix.sync.aligned.m8n8.x4.shared.b16 {%0,%1,%2,%3}, [%4];" \
                 : "=r"(r0), "=r"(r1), "=r"(r2), "=r"(r3) : "r"(addr))

__device__ __forceinline__ void mma16816(float* d, const uint32_t* a,
                                         const uint32_t* b) {
    asm volatile(
        "mma.sync.aligned.m16n8k16.row.col.f32.f16.f16.f32 "
        "{%0,%1,%2,%3}, {%4,%5,%6,%7}, {%8,%9}, {%0,%1,%2,%3};"
        : "+f"(d[0]), "+f"(d[1]), "+f"(d[2]), "+f"(d[3])
        : "r"(a[0]), "r"(a[1]), "r"(a[2]), "r"(a[3]), "r"(b[0]), "r"(b[1]));
}

// swizzles
__device__ __forceinline__ uint32_t g128(int r, int c) {  // r<128, c<8
    return (uint32_t)((r << 7) + ((c ^ (r & 7)) << 4));
}
__device__ __forceinline__ uint32_t qsw(int r, int c) {   // r<64, c<16
    return (uint32_t)((r << 8) + ((c ^ (r & 7)) << 4));
}
__device__ __forceinline__ uint32_t vsw(int r, int c) {   // r<128, c<8
    return (uint32_t)((r << 7) + ((c ^ (r & 7)) << 4));
}

__device__ __forceinline__ void split_h2(float a, float b, __half2& h, __half2& l)
{
    const __half h0 = __float2half(a), h1 = __float2half(b);
    h = __halves2half2(h0, h1);
    l = __halves2half2(__float2half(a - __half2float(h0)),
                       __float2half(b - __half2float(h1)));
}

// ---------------------------------------------------------------------------
// converts + RoPE tables
// ---------------------------------------------------------------------------
__global__ void mha_split16(const float* __restrict__ src,
                            __half* __restrict__ hi,
                            __half* __restrict__ lo, int n4)
{
    int i = blockIdx.x * blockDim.x + threadIdx.x;
    if (i >= n4) return;
    float4 v = ((const float4*)src)[i];
    __half2 h0, l0, h1, l1;
    split_h2(v.x, v.y, h0, l0);
    split_h2(v.z, v.w, h1, l1);
    ((__half2*)hi)[i * 2 + 0] = h0;
    ((__half2*)hi)[i * 2 + 1] = h1;
    ((__half2*)lo)[i * 2 + 0] = l0;
    ((__half2*)lo)[i * 2 + 1] = l1;
}

// 4 weight tensors in one launch (blockIdx.y selects)
__global__ void mha_cvt16x4(const float* __restrict__ s0, __half* __restrict__ d0,
                            const float* __restrict__ s1, __half* __restrict__ d1,
                            const float* __restrict__ s2, __half* __restrict__ d2,
                            const float* __restrict__ s3, __half* __restrict__ d3,
                            int n4)
{
    int i = blockIdx.x * blockDim.x + threadIdx.x;
    if (i >= n4) return;
    const float* src = (blockIdx.y == 0) ? s0 : (blockIdx.y == 1) ? s1
                       : (blockIdx.y == 2) ? s2 : s3;
    __half* dst = (blockIdx.y == 0) ? d0 : (blockIdx.y == 1) ? d1
                  : (blockIdx.y == 2) ? d2 : d3;
    float4 v = ((const float4*)src)[i];
    __half2* D = (__half2*)dst;
    D[i * 2 + 0] = __floats2half2_rn(v.x, v.y);
    D[i * 2 + 1] = __floats2half2_rn(v.z, v.w);
}

__global__ void mha_rope_tables(float* __restrict__ rc, float* __restrict__ rs)
{
    const int s = blockIdx.x;
    const int i = threadIdx.x;  // 0..63
    const int jc = (2 * i) & 63;
    const int js = (2 * i + 1) & 63;
    const float invc = powf(10000.0f, -(float)jc * (1.0f / 64.0f));
    const float invs = powf(10000.0f, -(float)js * (1.0f / 64.0f));
    rc[s * 64 + i] = cosf((float)s * invc);
    rs[s * 64 + i] = sinf((float)s * invs);
}

// ---------------------------------------------------------------------------
// Templated GEMM: C[m,n] = sum_k A[m,k]*B[n,k]. Tile 128x128, K-chunk 64,
// 128 thr = 4 warps (2m x 2n), per-warp 64x64 (cuts LDS reads 25% vs 8-warp).
// NPASS: 2 = (A_hi+A_lo)@B, 1 = A_hi@B.
// MODE: 0 = fp32 row-major out; 1 = RoPE+scale, fp16 hi/lo scatter (dual
//       launch: blockIdx.x>=16 uses B2/OH2/OL2/scale2); 2 = fp16 hi scatter.
// ---------------------------------------------------------------------------
#define GSTAGE 49152
#define GSMEM  (2 * GSTAGE)

template <int MODE, int NPASS>
__global__ __launch_bounds__(128, 2)
void gemm_t(const __half* __restrict__ Ahi, const __half* __restrict__ Alo,
            const __half* __restrict__ Bh, float* __restrict__ C,
            __half* __restrict__ OH, __half* __restrict__ OL, float scale,
            const float* __restrict__ rc, const float* __restrict__ rs,
            const __half* __restrict__ B2, __half* __restrict__ OH2,
            __half* __restrict__ OL2, float scale2)
{
    extern __shared__ char smg[];
    const uint32_t sbase = smem_u32(smg);
    const int K = D_MODEL;
    const int tid  = threadIdx.x;
    const int lane = tid & 31;
    const int wid  = tid >> 5;     // 0..3
    const int warp_m = wid & 1;    // 64-row slab
    const int warp_n = wid >> 1;   // 64-col slab
    const int m0 = blockIdx.y * 128;

    const __half* Bsel = Bh;
    __half* OHs = OH;
    __half* OLs = OL;
    float scl = scale;
    int nblk = blockIdx.x;
    if (MODE == 1 && nblk >= 16) {
        Bsel = B2; OHs = OH2; OLs = OL2; scl = scale2; nblk -= 16;
    }
    const int n0 = nblk * 128;

    float acc[4][8][4];
#pragma unroll
    for (int mt = 0; mt < 4; ++mt)
#pragma unroll
        for (int nt = 0; nt < 8; ++nt)
#pragma unroll
            for (int e = 0; e < 4; ++e) acc[mt][nt][e] = 0.f;

    auto load_chunk = [&](int kc, int s) {
        const uint32_t st = sbase + s * GSTAGE;
#pragma unroll
        for (int i = 0; i < 8; ++i) {
            const int idx = tid + i * 128;   // 0..1023
            const int r = idx >> 3;
            const int c = idx & 7;
            const uint32_t so = g128(r, c);
            const size_t ga = (size_t)(m0 + r) * K + kc + c * 8;
            const size_t gb = (size_t)(n0 + r) * K + kc + c * 8;
            cp16(st + so, Ahi + ga);
            if (NPASS == 2) cp16(st + 16384 + so, Alo + ga);
            cp16(st + 32768 + so, Bsel + gb);
        }
    };

    load_chunk(0, 0);
    CPC();

    const int nchunks = K / 64;
    for (int c = 0; c < nchunks; ++c) {
        const int buf = c & 1;
        if (c + 1 < nchunks) {
            load_chunk((c + 1) * 64, buf ^ 1);
            CPC();
            CPW(1);
        } else {
            CPW(0);
        }
        __syncthreads();

        const uint32_t ab_hi = sbase + buf * GSTAGE;
        const uint32_t ab_lo = ab_hi + 16384;
        const uint32_t bb_hi = ab_hi + 32768;

#pragma unroll
        for (int ks = 0; ks < 4; ++ks) {
            const int ch = ks * 2 + (lane >> 4);
            uint32_t ah[4][4], al[4][4];
#pragma unroll
            for (int mt = 0; mt < 4; ++mt) {
                const int r = warp_m * 64 + mt * 16 + (lane & 15);
                const uint32_t so = g128(r, ch);
                LDSM4(ah[mt][0], ah[mt][1], ah[mt][2], ah[mt][3], ab_hi + so);
                if (NPASS == 2)
                    LDSM4(al[mt][0], al[mt][1], al[mt][2], al[mt][3], ab_lo + so);
            }
            uint32_t bh[8][2];
#pragma unroll
            for (int nt2 = 0; nt2 < 4; ++nt2) {
                const int r = warp_n * 64 + nt2 * 16 + (lane & 15);
                const uint32_t so = g128(r, ch);
                uint32_t t0, t1, t2, t3;
                LDSM4(t0, t1, t2, t3, bb_hi + so);
                bh[nt2 * 2][0] = t0; bh[nt2 * 2][1] = t2;
                bh[nt2 * 2 + 1][0] = t1; bh[nt2 * 2 + 1][1] = t3;
            }
#pragma unroll
            for (int nt = 0; nt < 8; ++nt)
#pragma unroll
                for (int mt = 0; mt < 4; ++mt)
                    mma16816(acc[mt][nt], ah[mt], bh[nt]);
            if (NPASS == 2) {
#pragma unroll
                for (int nt = 0; nt < 8; ++nt)
#pragma unroll
                    for (int mt = 0; mt < 4; ++mt)
                        mma16816(acc[mt][nt], al[mt], bh[nt]);
            }
        }
        __syncthreads();
    }

    // --- epilogue ---
#pragma unroll
    for (int mt = 0; mt < 4; ++mt) {
#pragma unroll
        for (int half = 0; half < 2; ++half) {
            const int row = m0 + warp_m * 64 + mt * 16 + (lane >> 2) + half * 8;
#pragma unroll
            for (int nt = 0; nt < 8; ++nt) {
                const int col = n0 + warp_n * 64 + nt * 8 + (lane & 3) * 2;
                float v0 = acc[mt][nt][half * 2 + 0];
                float v1 = acc[mt][nt][half * 2 + 1];
                if (MODE == 0) {
                    *(float2*)&C[(size_t)row * D_MODEL + col] = make_float2(v0, v1);
                } else {
                    const int s  = row & (SEQ - 1);
                    const int b  = row >> 11;
                    const int hh = col >> 7;
                    const int dd = col & (HEAD_DIM - 1);
                    const size_t idx =
                        (((size_t)(b * N_HEADS + hh)) * SEQ + s) * HEAD_DIM + dd;
                    if (MODE == 1) {
                        const float cc = rc[s * 64 + (dd >> 1)];
                        const float sn = rs[s * 64 + (dd >> 1)];
                        const float r1 = (v0 * cc - v1 * sn) * scl;
                        const float r2 = (v0 * sn + v1 * cc) * scl;
                        __half2 h, l;
                        split_h2(r1, r2, h, l);
                        *(__half2*)&OHs[idx] = h;
                        *(__half2*)&OLs[idx] = l;
                    } else {  // MODE == 2: hi only
                        *(__half2*)&OHs[idx] = __floats2half2_rn(v0, v1);
                    }
                }
            }
        }
    }
}

// ---------------------------------------------------------------------------
// fp16 transpose (hi only): [bh][s][d] -> [bh][d][s]
// ---------------------------------------------------------------------------
__global__ void mha_t16(const __half* __restrict__ vh, __half* __restrict__ vth)
{
    __shared__ __half t[32][33];
    const int bh = blockIdx.z;
    const int s0 = blockIdx.x * 32;
    const int d0 = blockIdx.y * 32;
    const int tx = threadIdx.x, ty = threadIdx.y;  // (32, 8)
    const size_t ib = (size_t)bh * SEQ * HEAD_DIM;
#pragma unroll
    for (int i = 0; i < 4; ++i)
        t[ty + 8 * i][tx] = vh[ib + (size_t)(s0 + ty + 8 * i) * HEAD_DIM + d0 + tx];
    __syncthreads();
    const size_t ob = (size_t)bh * HEAD_DIM * SEQ;
#pragma unroll
    for (int i = 0; i < 4; ++i) {
        const int d = d0 + ty + 8 * i;
        vth[ob + (size_t)d * SEQ + s0 + tx] = t[tx][ty + 8 * i];
    }
}

// ---------------------------------------------------------------------------
// Tensor-core causal flash attention. QK^T 3-pass (logit path), PV 1-pass
// (P and V both linear-path fp16). Writes fp16 hi for the out GEMM.
// ---------------------------------------------------------------------------
#define FA_SQH 0
#define FA_SQL 16384
#define FA_SKH 32768
#define FA_SKL 49152
#define FA_SVH 65536
#define FA_SMEM 81920

__global__ __launch_bounds__(128, 2)
void mha_flash_mma(const __half* __restrict__ qh, const __half* __restrict__ ql,
                   const __half* __restrict__ kh, const __half* __restrict__ kl,
                   const __half* __restrict__ vth, __half* __restrict__ AH)
{
    extern __shared__ char smfa[];
    const uint32_t sb = smem_u32(smfa);
    const int tid  = threadIdx.x;
    const int lane = tid & 31;
    const int w    = tid >> 5;
    const int qb   = blockIdx.x;
    const int bh   = blockIdx.y;
    const int q0   = qb * 64;

    const size_t qoff = ((size_t)bh * SEQ + q0) * HEAD_DIM;
    const __half* Qh = qh + qoff;
    const __half* Ql = ql + qoff;
    const __half* Kb_h = kh + (size_t)bh * SEQ * HEAD_DIM;
    const __half* Kb_l = kl + (size_t)bh * SEQ * HEAD_DIM;
    const __half* Vb_h = vth + (size_t)bh * HEAD_DIM * SEQ;

#pragma unroll
    for (int i = 0; i < 8; ++i) {
        const int idx = tid + i * 128;
        const int r = idx >> 4;
        const int c = idx & 15;
        cp16(sb + FA_SQH + qsw(r, c), Qh + (size_t)r * HEAD_DIM + c * 8);
        cp16(sb + FA_SQL + qsw(r, c), Ql + (size_t)r * HEAD_DIM + c * 8);
    }

    float oacc[16][4];
#pragma unroll
    for (int nt = 0; nt < 16; ++nt)
#pragma unroll
        for (int e = 0; e < 4; ++e) oacc[nt][e] = 0.f;
    float m0v = -INFINITY, m1v = -INFINITY, l0v = 0.f, l1v = 0.f;

    for (int kb = 0; kb <= qb; ++kb) {
        const int k0 = kb * 64;
        __syncthreads();
#pragma unroll
        for (int i = 0; i < 8; ++i) {
            const int idx = tid + i * 128;
            const int r = idx >> 4;
            const int c = idx & 15;
            cp16(sb + FA_SKH + qsw(r, c), Kb_h + (size_t)(k0 + r) * HEAD_DIM + c * 8);
            cp16(sb + FA_SKL + qsw(r, c), Kb_l + (size_t)(k0 + r) * HEAD_DIM + c * 8);
            const int rv = idx >> 3;
            const int cv = idx & 7;
            cp16(sb + FA_SVH + vsw(rv, cv), Vb_h + (size_t)rv * SEQ + k0 + cv * 8);
        }
        CPC();
        CPW(0);
        __syncthreads();

        float sacc[8][4];
#pragma unroll
        for (int nt = 0; nt < 8; ++nt)
#pragma unroll
            for (int e = 0; e < 4; ++e) sacc[nt][e] = 0.f;

#pragma unroll
        for (int ks = 0; ks < 8; ++ks) {
            const int ch = ks * 2 + (lane >> 4);
            uint32_t aqh[4], aql[4];
            {
                const uint32_t so = qsw(16 * w + (lane & 15), ch);
                LDSM4(aqh[0], aqh[1], aqh[2], aqh[3], sb + FA_SQH + so);
                LDSM4(aql[0], aql[1], aql[2], aql[3], sb + FA_SQL + so);
            }
            uint32_t bkh[8][2], bkl[8][2];
#pragma unroll
            for (int nt2 = 0; nt2 < 4; ++nt2) {
                const uint32_t so = qsw(nt2 * 16 + (lane & 15), ch);
                uint32_t t0, t1, t2, t3;
                LDSM4(t0, t1, t2, t3, sb + FA_SKH + so);
                bkh[nt2 * 2][0] = t0; bkh[nt2 * 2][1] = t2;
                bkh[nt2 * 2 + 1][0] = t1; bkh[nt2 * 2 + 1][1] = t3;
                LDSM4(t0, t1, t2, t3, sb + FA_SKL + so);
                bkl[nt2 * 2][0] = t0; bkl[nt2 * 2][1] = t2;
                bkl[nt2 * 2 + 1][0] = t1; bkl[nt2 * 2 + 1][1] = t3;
            }
#pragma unroll
            for (int nt = 0; nt < 8; ++nt) {
                mma16816(sacc[nt], aqh, bkh[nt]);
                mma16816(sacc[nt], aqh, bkl[nt]);
                mma16816(sacc[nt], aql, bkh[nt]);
            }
        }

        const int row0 = q0 + 16 * w + (lane >> 2);
        if (kb == qb) {
#pragma unroll
            for (int nt = 0; nt < 8; ++nt)
#pragma unroll
                for (int e = 0; e < 4; ++e) {
                    const int col = k0 + nt * 8 + (lane & 3) * 2 + (e & 1);
                    const int row = row0 + (e >> 1) * 8;
                    if (col > row) sacc[nt][e] = -INFINITY;
                }
        }

        float rmax0 = -INFINITY, rmax1 = -INFINITY;
#pragma unroll
        for (int nt = 0; nt < 8; ++nt) {
            rmax0 = fmaxf(rmax0, fmaxf(sacc[nt][0], sacc[nt][1]));
            rmax1 = fmaxf(rmax1, fmaxf(sacc[nt][2], sacc[nt][3]));
        }
        rmax0 = fmaxf(rmax0, __shfl_xor_sync(0xffffffffu, rmax0, 1));
        rmax0 = fmaxf(rmax0, __shfl_xor_sync(0xffffffffu, rmax0, 2));
        rmax1 = fmaxf(rmax1, __shfl_xor_sync(0xffffffffu, rmax1, 1));
        rmax1 = fmaxf(rmax1, __shfl_xor_sync(0xffffffffu, rmax1, 2));
        const float mn0 = fmaxf(m0v, rmax0);
        const float mn1 = fmaxf(m1v, rmax1);
        const float al0 = __expf(m0v - mn0);
        const float al1 = __expf(m1v - mn1);
        m0v = mn0; m1v = mn1;
        float rs0 = 0.f, rs1 = 0.f;
#pragma unroll
        for (int nt = 0; nt < 8; ++nt) {
            sacc[nt][0] = __expf(sacc[nt][0] - mn0);
            sacc[nt][1] = __expf(sacc[nt][1] - mn0);
            sacc[nt][2] = __expf(sacc[nt][2] - mn1);
            sacc[nt][3] = __expf(sacc[nt][3] - mn1);
            rs0 += sacc[nt][0] + sacc[nt][1];
            rs1 += sacc[nt][2] + sacc[nt][3];
        }
        rs0 += __shfl_xor_sync(0xffffffffu, rs0, 1);
        rs0 += __shfl_xor_sync(0xffffffffu, rs0, 2);
        rs1 += __shfl_xor_sync(0xffffffffu, rs1, 1);
        rs1 += __shfl_xor_sync(0xffffffffu, rs1, 2);
        l0v = l0v * al0 + rs0;
        l1v = l1v * al1 + rs1;
#pragma unroll
        for (int nt = 0; nt < 16; ++nt) {
            oacc[nt][0] *= al0; oacc[nt][1] *= al0;
            oacc[nt][2] *= al1; oacc[nt][3] *= al1;
        }

        // P fragments, single fp16 (linear path)
        uint32_t pfh[4][4];
#pragma unroll
        for (int kc = 0; kc < 4; ++kc) {
#pragma unroll
            for (int e = 0; e < 4; ++e) {
                const int t  = 2 * kc + (e >> 1);
                const int e0 = (e & 1) * 2;
                const __half2 hv = __floats2half2_rn(sacc[t][e0], sacc[t][e0 + 1]);
                const int slot = ((e >> 1) << 1) | (e & 1);
                pfh[kc][slot] = *(const uint32_t*)&hv;
            }
        }

#pragma unroll
        for (int kc = 0; kc < 4; ++kc) {
#pragma unroll
            for (int g = 0; g < 8; ++g) {
                const uint32_t so = vsw(g * 16 + (lane & 15), kc * 2 + (lane >> 4));
                uint32_t t0, t1, t2, t3;
                uint32_t b0h[2], b1h[2];
                LDSM4(t0, t1, t2, t3, sb + FA_SVH + so);
                b0h[0] = t0; b0h[1] = t2; b1h[0] = t1; b1h[1] = t3;
                mma16816(oacc[2 * g],     pfh[kc], b0h);
                mma16816(oacc[2 * g + 1], pfh[kc], b1h);
            }
        }
    }

    const float inv0 = 1.0f / l0v;
    const float inv1 = 1.0f / l1v;
    const int b = bh >> 4;
    const int h = bh & 15;
    const int row0 = q0 + 16 * w + (lane >> 2);
#pragma unroll
    for (int nt = 0; nt < 16; ++nt) {
        const int col = h * HEAD_DIM + nt * 8 + (lane & 3) * 2;
        const size_t i0 = ((size_t)(b * SEQ + row0)) * D_MODEL + col;
        const size_t i1 = ((size_t)(b * SEQ + row0 + 8)) * D_MODEL + col;
        *(__half2*)&AH[i0] = __floats2half2_rn(oacc[nt][0] * inv0,
                                               oacc[nt][1] * inv0);
        *(__half2*)&AH[i1] = __floats2half2_rn(oacc[nt][2] * inv1,
                                               oacc[nt][3] * inv1);
    }
}

// ---------------------------------------------------------------------------
// Launch
// ---------------------------------------------------------------------------
extern "C" void kernel_launch(void* const* d_in, const int* in_sizes, int n_in,
                              void* d_out, int out_size)
{
    (void)in_sizes; (void)n_in; (void)out_size;
    const float* x  = (const float*)d_in[0];
    const float* wq = (const float*)d_in[1];
    const float* wk = (const float*)d_in[2];
    const float* wv = (const float*)d_in[3];
    const float* wo = (const float*)d_in[4];
    float* out = (float*)d_out;

    __half *xh, *xl, *ah, *wqh, *wkh, *wvh, *woh;
    cudaGetSymbolAddress((void**)&xh, g_x_hi);
    cudaGetSymbolAddress((void**)&xl, g_x_lo);
    cudaGetSymbolAddress((void**)&ah, g_a_hi);
    cudaGetSymbolAddress((void**)&wqh, g_wq_h);
    cudaGetSymbolAddress((void**)&wkh, g_wk_h);
    cudaGetSymbolAddress((void**)&wvh, g_wv_h);
    cudaGetSymbolAddress((void**)&woh, g_wo_h);

    __half *q16h, *q16l, *k16h, *k16l, *v16h, *vt16h;
    cudaGetSymbolAddress((void**)&q16h, g_q16h);
    cudaGetSymbolAddress((void**)&q16l, g_q16l);
    cudaGetSymbolAddress((void**)&k16h, g_k16h);
    cudaGetSymbolAddress((void**)&k16l, g_k16l);
    cudaGetSymbolAddress((void**)&v16h, g_v16h);
    cudaGetSymbolAddress((void**)&vt16h, g_vt16h);

    float *rc, *rs;
    cudaGetSymbolAddress((void**)&rc, g_ropec);
    cudaGetSymbolAddress((void**)&rs, g_ropes);

    const int nx4 = M_ROWS * D_MODEL / 4;
    const int nw4 = D_MODEL * D_MODEL / 4;

    mha_split16<<<nx4 / 256, 256>>>(x, xh, xl, nx4);
    mha_cvt16x4<<<dim3(nw4 / 256, 4), 256>>>(wq, wqh, wk, wkh, wv, wvh, wo, woh,
                                             nw4);
    mha_rope_tables<<<SEQ, 64>>>(rc, rs);

    cudaFuncSetAttribute(gemm_t<0, 1>, cudaFuncAttributeMaxDynamicSharedMemorySize,
                         GSMEM);
    cudaFuncSetAttribute(gemm_t<1, 2>, cudaFuncAttributeMaxDynamicSharedMemorySize,
                         GSMEM);
    cudaFuncSetAttribute(gemm_t<2, 1>, cudaFuncAttributeMaxDynamicSharedMemorySize,
                         GSMEM);
    const dim3 gg(D_MODEL / 128, M_ROWS / 128);

    // Q and K in one launch (blockIdx.x>=16 -> K side)
    gemm_t<1, 2><<<dim3(32, M_ROWS / 128), 128, GSMEM>>>(
        xh, xl, wqh, nullptr, q16h, q16l, 0.08838834764831845f, rc, rs,
        wkh, k16h, k16l, 1.0f);
    gemm_t<2, 1><<<gg, 128, GSMEM>>>(xh, nullptr, wvh, nullptr, v16h, nullptr,
                                     1.0f, rc, rs, nullptr, nullptr, nullptr, 0.f);

    mha_t16<<<dim3(SEQ / 32, HEAD_DIM / 32, BH), dim3(32, 8)>>>(v16h, vt16h);

    cudaFuncSetAttribute(mha_flash_mma, cudaFuncAttributeMaxDynamicSharedMemorySize,
                         FA_SMEM);
    mha_flash_mma<<<dim3(SEQ / 64, BH), 128, FA_SMEM>>>(q16h, q16l, k16h, k16l,
                                                        vt16h, ah);

    gemm_t<0, 1><<<gg, 128, GSMEM>>>(ah, nullptr, woh, out, nullptr, nullptr,
                                     1.0f, rc, rs, nullptr, nullptr, nullptr, 0.f);
}